// round 6
// baseline (speedup 1.0000x reference)
#include <cuda_runtime.h>
#include <math.h>

// ---------------- problem constants ----------------
#define TSQ   512
#define BATCH 64
#define INP   256
#define HID   1024
#define OUTD  256
#define DT_A  0.05f

// output buffer layout (floats): [output_tensor | input_proj | tot_rnnhid | tot_output]
static const size_t O_OUTT = 0;                                  // (512,64,256)
static const size_t O_IP   = (size_t)TSQ * BATCH * OUTD;         // (64,512,1024)
static const size_t O_HID  = O_IP  + (size_t)BATCH * TSQ * HID;  // (64,512,1024)
static const size_t O_OUT  = O_HID + (size_t)BATCH * TSQ * HID;  // (64,512,256)

// flag padding: one counter per 128-byte L2 line
#define FPAD 32

// ---------------- device scratch (static: no allocations allowed) ----------------
__device__ float    g_thT [(size_t)TSQ * BATCH * HID];   // tf32(tanh h): [t][b][k] (MMA A layout)
__device__ float    g_thbt[(size_t)BATCH * TSQ * HID];   // fp32 tanh(h): [b][t][k] (output-GEMM layout)
__device__ float    g_part[2 * 128 * 4096];              // split-K partials (fragment layout), dbl-buffered
__device__ unsigned g_pflag[TSQ * 16 * FPAD];            // partials-ready counters (per t, col-tile)
__device__ unsigned g_tflag[TSQ * 16 * FPAD];            // th-ready counters (per t, col-tile)

// ---------------- f32x2 packed-FMA helpers (for kernels A/C) ----------------
__device__ __forceinline__ unsigned long long pack2(float v) {
    unsigned long long r;
    asm("mov.b64 %0, {%1, %1};" : "=l"(r) : "r"(__float_as_uint(v)));
    return r;
}
__device__ __forceinline__ void fma2(unsigned long long& d, unsigned long long a, unsigned long long b) {
    asm("fma.rn.f32x2 %0, %1, %2, %0;" : "+l"(d) : "l"(a), "l"(b));
}
__device__ __forceinline__ float2 unpack2(unsigned long long v) {
    unsigned lo, hi;
    asm("mov.b64 {%0, %1}, %2;" : "=r"(lo), "=r"(hi) : "l"(v));
    return make_float2(__uint_as_float(lo), __uint_as_float(hi));
}

// ---------------- sync helpers ----------------
__device__ __forceinline__ unsigned ld_acq(const unsigned* p) {
    unsigned v;
    asm volatile("ld.acquire.gpu.global.u32 %0, [%1];" : "=r"(v) : "l"(p) : "memory");
    return v;
}
__device__ __forceinline__ void red_rel_add(unsigned* p, unsigned v) {
    asm volatile("red.release.gpu.global.add.u32 [%0], %1;" :: "l"(p), "r"(v) : "memory");
}

// ---------------- tf32 helpers ----------------
__device__ __forceinline__ unsigned cvt_tf32(float f) {
    unsigned u;
    asm("cvt.rna.tf32.f32 %0, %1;" : "=r"(u) : "f"(f));
    return u;
}
__device__ __forceinline__ void mma_tf32(float d[4], unsigned a0, unsigned a1, unsigned a2, unsigned a3,
                                         unsigned b0, unsigned b1) {
    asm volatile(
        "mma.sync.aligned.m16n8k8.row.col.f32.tf32.tf32.f32 "
        "{%0,%1,%2,%3}, {%4,%5,%6,%7}, {%8,%9}, {%0,%1,%2,%3};"
        : "+f"(d[0]), "+f"(d[1]), "+f"(d[2]), "+f"(d[3])
        : "r"(a0), "r"(a1), "r"(a2), "r"(a3), "r"(b0), "r"(b1));
}

// =====================================================================
// Kernel A: input_proj[b][t][h] = sum_i x[t][b][i] * Win[i][h]
// =====================================================================
#define BM 128
#define BN 64
#define BK 16
#define AS_LD 136

__global__ __launch_bounds__(256) void input_proj_kernel(
    const float* __restrict__ x, const float* __restrict__ Win, float* __restrict__ ip)
{
    __shared__ float As[BK * AS_LD];
    __shared__ float Bs[BK * BN];

    const int tid = threadIdx.x;
    const int r0  = blockIdx.y * BM;
    const int c0  = blockIdx.x * BN;
    const int b   = r0 >> 9;
    const int t0  = r0 & 511;

    const int arow = tid >> 2;
    const int ac4  = tid & 3;
    const int brow = tid >> 4;
    const int bc4  = tid & 15;
    const int tx = tid & 15;
    const int ty = tid >> 4;

    unsigned long long acc[4][4];
#pragma unroll
    for (int i = 0; i < 4; i++)
#pragma unroll
        for (int j = 0; j < 4; j++) acc[i][j] = 0ull;

    for (int k0 = 0; k0 < INP; k0 += BK) {
#pragma unroll
        for (int p = 0; p < 2; p++) {
            const int row = arow + p * 64;
            const float4 v = *(const float4*)&x[((size_t)(t0 + row) * BATCH + b) * INP + k0 + ac4 * 4];
            As[(ac4 * 4 + 0) * AS_LD + row] = v.x;
            As[(ac4 * 4 + 1) * AS_LD + row] = v.y;
            As[(ac4 * 4 + 2) * AS_LD + row] = v.z;
            As[(ac4 * 4 + 3) * AS_LD + row] = v.w;
        }
        *(float4*)&Bs[brow * BN + bc4 * 4] =
            *(const float4*)&Win[(size_t)(k0 + brow) * HID + c0 + bc4 * 4];
        __syncthreads();

#pragma unroll
        for (int k = 0; k < BK; k++) {
            const ulonglong2 a01 = *(const ulonglong2*)&As[k * AS_LD + ty * 8];
            const ulonglong2 a23 = *(const ulonglong2*)&As[k * AS_LD + ty * 8 + 4];
            const float4 bf = *(const float4*)&Bs[k * BN + tx * 4];
            const unsigned long long b0 = pack2(bf.x), b1 = pack2(bf.y),
                                     b2 = pack2(bf.z), b3 = pack2(bf.w);
            fma2(acc[0][0], a01.x, b0); fma2(acc[0][1], a01.x, b1);
            fma2(acc[0][2], a01.x, b2); fma2(acc[0][3], a01.x, b3);
            fma2(acc[1][0], a01.y, b0); fma2(acc[1][1], a01.y, b1);
            fma2(acc[1][2], a01.y, b2); fma2(acc[1][3], a01.y, b3);
            fma2(acc[2][0], a23.x, b0); fma2(acc[2][1], a23.x, b1);
            fma2(acc[2][2], a23.x, b2); fma2(acc[2][3], a23.x, b3);
            fma2(acc[3][0], a23.y, b0); fma2(acc[3][1], a23.y, b1);
            fma2(acc[3][2], a23.y, b2); fma2(acc[3][3], a23.y, b3);
        }
        __syncthreads();
    }

#pragma unroll
    for (int rp = 0; rp < 4; rp++) {
        const int r = r0 + ty * 8 + 2 * rp;
        const float2 u0 = unpack2(acc[rp][0]), u1 = unpack2(acc[rp][1]);
        const float2 u2 = unpack2(acc[rp][2]), u3 = unpack2(acc[rp][3]);
        *(float4*)&ip[(size_t)r * HID + c0 + tx * 4]       = make_float4(u0.x, u1.x, u2.x, u3.x);
        *(float4*)&ip[(size_t)(r + 1) * HID + c0 + tx * 4] = make_float4(u0.y, u1.y, u2.y, u3.y);
    }
}

// =====================================================================
// Kernel B: persistent split-K recurrent scan with tf32 mma.sync.
// 128 CTAs: kc = bid>>4 (K-chunk of 128), ct = bid&15 (64-col tile).
// Per step: wait th(t-1) -> stage A=th[b][k] -> tf32 MMA (64x64, K=128) ->
// store fragment partials -> flag -> wait 8 partials -> reduce (b,c,c+1) ->
// h update + tanh -> store th -> flag.
// =====================================================================
#define ALD 132   // padded smem row stride (floats) -> conflict-free fragment loads

__global__ __launch_bounds__(256) void rnn_scan_kernel(
    const float* __restrict__ ip, const float* __restrict__ Wr,
    const float* __restrict__ bias, float* __restrict__ hid)
{
    extern __shared__ float smem[];
    float* As = smem;              // [64][132] tf32(th) slice for this step
    float* Bs = smem + 64 * ALD;   // [64][132] tf32(Wr^T) persistent slice
    unsigned* Asu = (unsigned*)As;
    unsigned* Bsu = (unsigned*)Bs;

    const int tid = threadIdx.x;
    const int bid = blockIdx.x;     // 0..127
    const int kc  = bid >> 4;       // 0..7
    const int ct  = bid & 15;       // 0..15

    // ---- persistent B operand: Bs[c][k] = tf32(Wr[(kc*128+k)*1024 + ct*64 + c]) ----
#pragma unroll
    for (int ii = 0; ii < 8; ii++) {
        const int idx = tid + 256 * ii;        // 0..2047
        const int k = idx >> 4, c4 = idx & 15;
        const float4 v = __ldg((const float4*)&Wr[(size_t)(kc * 128 + k) * HID + ct * 64 + c4 * 4]);
        Bsu[(c4 * 4 + 0) * ALD + k] = cvt_tf32(v.x);
        Bsu[(c4 * 4 + 1) * ALD + k] = cvt_tf32(v.y);
        Bsu[(c4 * 4 + 2) * ALD + k] = cvt_tf32(v.z);
        Bsu[(c4 * 4 + 3) * ALD + k] = cvt_tf32(v.w);
    }

    // ---- MMA thread coords: 8 warps tile 64x64 as (4 m-groups x 2 n-groups) ----
    const int w    = tid >> 5;
    const int lane = tid & 31;
    const int m0 = (w & 3) * 16;
    const int n0 = (w >> 2) * 32;
    const int lr = lane >> 2;
    const int lc = lane & 3;

    // ---- reducer coords: this thread owns (b, c, c+1) ----
    const int b  = kc * 8 + (tid >> 5);
    const int cl = (tid & 31) * 2;            // local col (even)
    const int c  = ct * 64 + cl;
    const float2 biav = *(const float2*)&bias[c];
    // fragment reverse-map index for (b, cl) within a producer's 4096-float block
    {
    }
    const int fw    = (b >> 4) + ((cl >> 5) << 2);
    const int fr    = b & 15;
    const int fcc   = cl & 31;
    const int fidx  = fw * 512 + (fcc >> 3) * 128 + ((fr & 7) * 4 + ((fcc & 7) >> 1)) * 4 + 2 * (fr >> 3);

    float h0 = 0.f, h1 = 0.f;

    __syncthreads();

    for (int t = 0; t < TSQ; t++) {
        // prefetch ip for this step (independent of t-1 data)
        const size_t i0 = ((size_t)b * TSQ + t) * HID + c;
        const float2 ipv = *(const float2*)&ip[i0];

        float s0 = 0.f, s1 = 0.f;
        if (t > 0) {
            // ---- wait for th col-tiles 2kc, 2kc+1 of step t-1 ----
            const unsigned* f0 = &g_tflag[(size_t)((t - 1) * 16 + 2 * kc) * FPAD];
            const unsigned* f1 = f0 + FPAD;
            while (ld_acq(f0) < 8u) { }
            while (ld_acq(f1) < 8u) { }

            // ---- stage A = th[b][k], k in [128kc, +128), padded rows ----
#pragma unroll
            for (int ii = 0; ii < 8; ii++) {
                const int idx = tid + 256 * ii;    // 0..2047 float4s
                const int br = idx >> 5, k4 = idx & 31;
                const float4 v = __ldcg((const float4*)&g_thT[((size_t)(t - 1) * BATCH + br) * HID + kc * 128 + k4 * 4]);
                *(float4*)&As[br * ALD + k4 * 4] = v;
            }
            __syncthreads();

            // ---- tf32 MMA: D[64x64] partial over K=128 ----
            float d[4][4];
#pragma unroll
            for (int j = 0; j < 4; j++)
#pragma unroll
                for (int r = 0; r < 4; r++) d[j][r] = 0.f;

#pragma unroll
            for (int k8 = 0; k8 < 16; k8++) {
                const int kb = k8 * 8;
                const unsigned a0 = Asu[(m0 + lr) * ALD + kb + lc];
                const unsigned a1 = Asu[(m0 + lr + 8) * ALD + kb + lc];
                const unsigned a2 = Asu[(m0 + lr) * ALD + kb + lc + 4];
                const unsigned a3 = Asu[(m0 + lr + 8) * ALD + kb + lc + 4];
#pragma unroll
                for (int j = 0; j < 4; j++) {
                    const unsigned b0 = Bsu[(n0 + j * 8 + lr) * ALD + kb + lc];
                    const unsigned b1 = Bsu[(n0 + j * 8 + lr) * ALD + kb + lc + 4];
                    mma_tf32(d[j], a0, a1, a2, a3, b0, b1);
                }
            }
            __syncthreads();   // As reusable next step; also orders before flag path

            // ---- store fragment partials (coalesced), double-buffered by parity ----
            float* gp = g_part + (size_t)(t & 1) * (128 * 4096) + (size_t)bid * 4096 + w * 512 + lane * 4;
#pragma unroll
            for (int j = 0; j < 4; j++)
                *(float4*)&gp[j * 128] = make_float4(d[j][0], d[j][1], d[j][2], d[j][3]);
            __threadfence();
            __syncthreads();
            if (tid == 0) red_rel_add(&g_pflag[(size_t)(t * 16 + ct) * FPAD], 1u);

            // ---- wait all 8 K-chunk partials of this col-tile ----
            const unsigned* fp = &g_pflag[(size_t)(t * 16 + ct) * FPAD];
            while (ld_acq(fp) < 8u) { }

            // ---- reduce: 8 fragment-mapped float2 reads ----
            const float* gpb = g_part + (size_t)(t & 1) * (128 * 4096);
#pragma unroll
            for (int q = 0; q < 8; q++) {
                const float2 p = __ldcg((const float2*)&gpb[(size_t)(q * 16 + ct) * 4096 + fidx]);
                s0 += p.x; s1 += p.y;
            }
        }

        // ---- state update for (b, c) and (b, c+1) ----
        h0 = (1.f - DT_A) * h0 + DT_A * (s0 + ipv.x + biav.x);
        h1 = (1.f - DT_A) * h1 + DT_A * (s1 + ipv.y + biav.y);
        *(float2*)&hid[i0] = make_float2(h0, h1);
        const float th0 = tanhf(h0), th1 = tanhf(h1);
        *(float2*)&g_thbt[i0] = make_float2(th0, th1);   // fp32 tanh for output GEMM
        // tf32-rounded tanh for next-step MMA A operand, [t][b][k] layout
        *(float2*)&g_thT[((size_t)t * BATCH + b) * HID + c] =
            make_float2(__uint_as_float(cvt_tf32(th0)), __uint_as_float(cvt_tf32(th1)));

        __threadfence();
        __syncthreads();
        if (tid == 0) red_rel_add(&g_tflag[(size_t)(t * 16 + ct) * FPAD], 1u);
    }
}

// =====================================================================
// Kernel C: tot_output = tanh(hid) @ Wout  (fp32 tanh cached in g_thbt),
// plus transposed copy output_tensor[t][b][o].  FFMA2.
// =====================================================================
__global__ __launch_bounds__(256) void output_kernel(
    const float* __restrict__ Wout, float* __restrict__ tot_out, float* __restrict__ outT)
{
    __shared__ float As[BK * AS_LD];
    __shared__ float Bs[BK * BN];

    const int tid = threadIdx.x;
    const int r0  = blockIdx.y * BM;
    const int c0  = blockIdx.x * BN;

    const int arow = tid >> 2;
    const int ac4  = tid & 3;
    const int brow = tid >> 4;
    const int bc4  = tid & 15;
    const int tx = tid & 15;
    const int ty = tid >> 4;

    unsigned long long acc[4][4];
#pragma unroll
    for (int i = 0; i < 4; i++)
#pragma unroll
        for (int j = 0; j < 4; j++) acc[i][j] = 0ull;

    for (int k0 = 0; k0 < HID; k0 += BK) {
#pragma unroll
        for (int p = 0; p < 2; p++) {
            const int row = arow + p * 64;
            const float4 v = *(const float4*)&g_thbt[(size_t)(r0 + row) * HID + k0 + ac4 * 4];
            As[(ac4 * 4 + 0) * AS_LD + row] = v.x;
            As[(ac4 * 4 + 1) * AS_LD + row] = v.y;
            As[(ac4 * 4 + 2) * AS_LD + row] = v.z;
            As[(ac4 * 4 + 3) * AS_LD + row] = v.w;
        }
        *(float4*)&Bs[brow * BN + bc4 * 4] =
            *(const float4*)&Wout[(size_t)(k0 + brow) * OUTD + c0 + bc4 * 4];
        __syncthreads();

#pragma unroll
        for (int k = 0; k < BK; k++) {
            const ulonglong2 a01 = *(const ulonglong2*)&As[k * AS_LD + ty * 8];
            const ulonglong2 a23 = *(const ulonglong2*)&As[k * AS_LD + ty * 8 + 4];
            const float4 bf = *(const float4*)&Bs[k * BN + tx * 4];
            const unsigned long long b0 = pack2(bf.x), b1 = pack2(bf.y),
                                     b2 = pack2(bf.z), b3 = pack2(bf.w);
            fma2(acc[0][0], a01.x, b0); fma2(acc[0][1], a01.x, b1);
            fma2(acc[0][2], a01.x, b2); fma2(acc[0][3], a01.x, b3);
            fma2(acc[1][0], a01.y, b0); fma2(acc[1][1], a01.y, b1);
            fma2(acc[1][2], a01.y, b2); fma2(acc[1][3], a01.y, b3);
            fma2(acc[2][0], a23.x, b0); fma2(acc[2][1], a23.x, b1);
            fma2(acc[2][2], a23.x, b2); fma2(acc[2][3], a23.x, b3);
            fma2(acc[3][0], a23.y, b0); fma2(acc[3][1], a23.y, b1);
            fma2(acc[3][2], a23.y, b2); fma2(acc[3][3], a23.y, b3);
        }
        __syncthreads();
    }

#pragma unroll
    for (int rp = 0; rp < 4; rp++) {
        const int r  = r0 + ty * 8 + 2 * rp;
        const float2 u0 = unpack2(acc[rp][0]), u1 = unpack2(acc[rp][1]);
        const float2 u2 = unpack2(acc[rp][2]), u3 = unpack2(acc[rp][3]);
        const float4 v0 = make_float4(u0.x, u1.x, u2.x, u3.x);
        const float4 v1 = make_float4(u0.y, u1.y, u2.y, u3.y);
        const int b0i = r >> 9,        t0i = r & 511;
        const int b1i = (r + 1) >> 9,  t1i = (r + 1) & 511;
        *(float4*)&tot_out[(size_t)r * OUTD + c0 + tx * 4]       = v0;
        *(float4*)&tot_out[(size_t)(r + 1) * OUTD + c0 + tx * 4] = v1;
        *(float4*)&outT[((size_t)t0i * BATCH + b0i) * OUTD + c0 + tx * 4] = v0;
        *(float4*)&outT[((size_t)t1i * BATCH + b1i) * OUTD + c0 + tx * 4] = v1;
    }
}

// =====================================================================
// launch
// =====================================================================
extern "C" void kernel_launch(void* const* d_in, const int* in_sizes, int n_in,
                              void* d_out, int out_size)
{
    const float* x    = (const float*)d_in[0];
    const float* Win  = (const float*)d_in[1];
    const float* Wr   = (const float*)d_in[2];
    const float* bias = (const float*)d_in[3];
    const float* Wout = (const float*)d_in[4];

    float* out    = (float*)d_out;
    float* o_outT = out + O_OUTT;
    float* o_ip   = out + O_IP;
    float* o_hid  = out + O_HID;
    float* o_out  = out + O_OUT;

    // reset flag counters each launch (graph-capturable, deterministic replays)
    void* p0 = nullptr; void* p1 = nullptr;
    cudaGetSymbolAddress(&p0, g_pflag);
    cudaGetSymbolAddress(&p1, g_tflag);
    cudaMemsetAsync(p0, 0, (size_t)TSQ * 16 * FPAD * sizeof(unsigned));
    cudaMemsetAsync(p1, 0, (size_t)TSQ * 16 * FPAD * sizeof(unsigned));

    const int smemB = 2 * 64 * ALD * (int)sizeof(float);  // 67584
    cudaFuncSetAttribute(rnn_scan_kernel, cudaFuncAttributeMaxDynamicSharedMemorySize, smemB);

    // 1) input projection
    input_proj_kernel<<<dim3(HID / BN, (TSQ * BATCH) / BM), 256>>>(x, Win, o_ip);

    // 2) persistent split-K recurrent scan: 128 CTAs (all resident in wave 1)
    rnn_scan_kernel<<<128, 256, smemB>>>(o_ip, Wr, bias, o_hid);

    // 3) output projection + transpose
    output_kernel<<<dim3(OUTD / BN, (TSQ * BATCH) / BM), 256>>>(Wout, o_out, o_outT);
}

// round 8
// speedup vs baseline: 1.4017x; 1.4017x over previous
#include <cuda_runtime.h>
#include <math.h>

// ---------------- problem constants ----------------
#define TSQ   512
#define BATCH 64
#define INP   256
#define HID   1024
#define OUTD  256
#define DT_A  0.05f

// output buffer layout (floats): [output_tensor | input_proj | tot_rnnhid | tot_output]
static const size_t O_OUTT = 0;                                  // (512,64,256)
static const size_t O_IP   = (size_t)TSQ * BATCH * OUTD;         // (64,512,1024)
static const size_t O_HID  = O_IP  + (size_t)BATCH * TSQ * HID;  // (64,512,1024)
static const size_t O_OUT  = O_HID + (size_t)BATCH * TSQ * HID;  // (64,512,256)

// flag padding: one counter per 128-byte L2 line
#define FPAD 32

// ---------------- device scratch (static: no allocations allowed) ----------------
__device__ float    g_thT [(size_t)TSQ * BATCH * HID];   // tf32(tanh h): [t][b][k] (MMA A layout)
__device__ float    g_thbt[(size_t)BATCH * TSQ * HID];   // fp32 tanh(h): [b][t][k] (output-GEMM layout)
__device__ float    g_part[2 * 128 * 4096];              // split-K partials (fragment layout), dbl-buffered
__device__ unsigned g_pflag[TSQ * 16 * FPAD];            // partials-ready counters (per t, col-tile), 8 arrivals
__device__ unsigned g_tflag[TSQ * 8 * FPAD];             // th-ready counters (per t, k-chunk), 16 arrivals

// ---------------- f32x2 packed-FMA helpers (for kernels A/C) ----------------
__device__ __forceinline__ unsigned long long pack2(float v) {
    unsigned long long r;
    asm("mov.b64 %0, {%1, %1};" : "=l"(r) : "r"(__float_as_uint(v)));
    return r;
}
__device__ __forceinline__ void fma2(unsigned long long& d, unsigned long long a, unsigned long long b) {
    asm("fma.rn.f32x2 %0, %1, %2, %0;" : "+l"(d) : "l"(a), "l"(b));
}
__device__ __forceinline__ float2 unpack2(unsigned long long v) {
    unsigned lo, hi;
    asm("mov.b64 {%0, %1}, %2;" : "=r"(lo), "=r"(hi) : "l"(v));
    return make_float2(__uint_as_float(lo), __uint_as_float(hi));
}

// ---------------- sync helpers ----------------
__device__ __forceinline__ unsigned ld_relax(const unsigned* p) {
    unsigned v;
    asm volatile("ld.relaxed.gpu.global.u32 %0, [%1];" : "=r"(v) : "l"(p) : "memory");
    return v;
}
__device__ __forceinline__ unsigned ld_acq(const unsigned* p) {
    unsigned v;
    asm volatile("ld.acquire.gpu.global.u32 %0, [%1];" : "=r"(v) : "l"(p) : "memory");
    return v;
}
__device__ __forceinline__ void red_rel_add(unsigned* p, unsigned v) {
    asm volatile("red.release.gpu.global.add.u32 [%0], %1;" :: "l"(p), "r"(v) : "memory");
}
// relaxed poll with nanosleep backoff, then one acquire load to establish ordering
__device__ __forceinline__ void wait_flag(const unsigned* p, unsigned target) {
    if (ld_relax(p) < target) {
        do { __nanosleep(100); } while (ld_relax(p) < target);
    }
    (void)ld_acq(p);   // flag is monotonic: acquire-read here synchronizes with the releases
}

// ---------------- tf32 helpers ----------------
__device__ __forceinline__ unsigned cvt_tf32(float f) {
    unsigned u;
    asm("cvt.rna.tf32.f32 %0, %1;" : "=r"(u) : "f"(f));
    return u;
}
__device__ __forceinline__ void mma_tf32(float d[4], unsigned a0, unsigned a1, unsigned a2, unsigned a3,
                                         unsigned b0, unsigned b1) {
    asm volatile(
        "mma.sync.aligned.m16n8k8.row.col.f32.tf32.tf32.f32 "
        "{%0,%1,%2,%3}, {%4,%5,%6,%7}, {%8,%9}, {%0,%1,%2,%3};"
        : "+f"(d[0]), "+f"(d[1]), "+f"(d[2]), "+f"(d[3])
        : "r"(a0), "r"(a1), "r"(a2), "r"(a3), "r"(b0), "r"(b1));
}

// =====================================================================
// Kernel A: input_proj[b][t][h] = sum_i x[t][b][i] * Win[i][h]
// =====================================================================
#define BM 128
#define BN 64
#define BK 16
#define AS_LD 136

__global__ __launch_bounds__(256) void input_proj_kernel(
    const float* __restrict__ x, const float* __restrict__ Win, float* __restrict__ ip)
{
    __shared__ float As[BK * AS_LD];
    __shared__ float Bs[BK * BN];

    const int tid = threadIdx.x;
    const int r0  = blockIdx.y * BM;
    const int c0  = blockIdx.x * BN;
    const int b   = r0 >> 9;
    const int t0  = r0 & 511;

    const int arow = tid >> 2;
    const int ac4  = tid & 3;
    const int brow = tid >> 4;
    const int bc4  = tid & 15;
    const int tx = tid & 15;
    const int ty = tid >> 4;

    unsigned long long acc[4][4];
#pragma unroll
    for (int i = 0; i < 4; i++)
#pragma unroll
        for (int j = 0; j < 4; j++) acc[i][j] = 0ull;

    for (int k0 = 0; k0 < INP; k0 += BK) {
#pragma unroll
        for (int p = 0; p < 2; p++) {
            const int row = arow + p * 64;
            const float4 v = *(const float4*)&x[((size_t)(t0 + row) * BATCH + b) * INP + k0 + ac4 * 4];
            As[(ac4 * 4 + 0) * AS_LD + row] = v.x;
            As[(ac4 * 4 + 1) * AS_LD + row] = v.y;
            As[(ac4 * 4 + 2) * AS_LD + row] = v.z;
            As[(ac4 * 4 + 3) * AS_LD + row] = v.w;
        }
        *(float4*)&Bs[brow * BN + bc4 * 4] =
            *(const float4*)&Win[(size_t)(k0 + brow) * HID + c0 + bc4 * 4];
        __syncthreads();

#pragma unroll
        for (int k = 0; k < BK; k++) {
            const ulonglong2 a01 = *(const ulonglong2*)&As[k * AS_LD + ty * 8];
            const ulonglong2 a23 = *(const ulonglong2*)&As[k * AS_LD + ty * 8 + 4];
            const float4 bf = *(const float4*)&Bs[k * BN + tx * 4];
            const unsigned long long b0 = pack2(bf.x), b1 = pack2(bf.y),
                                     b2 = pack2(bf.z), b3 = pack2(bf.w);
            fma2(acc[0][0], a01.x, b0); fma2(acc[0][1], a01.x, b1);
            fma2(acc[0][2], a01.x, b2); fma2(acc[0][3], a01.x, b3);
            fma2(acc[1][0], a01.y, b0); fma2(acc[1][1], a01.y, b1);
            fma2(acc[1][2], a01.y, b2); fma2(acc[1][3], a01.y, b3);
            fma2(acc[2][0], a23.x, b0); fma2(acc[2][1], a23.x, b1);
            fma2(acc[2][2], a23.x, b2); fma2(acc[2][3], a23.x, b3);
            fma2(acc[3][0], a23.y, b0); fma2(acc[3][1], a23.y, b1);
            fma2(acc[3][2], a23.y, b2); fma2(acc[3][3], a23.y, b3);
        }
        __syncthreads();
    }

#pragma unroll
    for (int rp = 0; rp < 4; rp++) {
        const int r = r0 + ty * 8 + 2 * rp;
        const float2 u0 = unpack2(acc[rp][0]), u1 = unpack2(acc[rp][1]);
        const float2 u2 = unpack2(acc[rp][2]), u3 = unpack2(acc[rp][3]);
        *(float4*)&ip[(size_t)r * HID + c0 + tx * 4]       = make_float4(u0.x, u1.x, u2.x, u3.x);
        *(float4*)&ip[(size_t)(r + 1) * HID + c0 + tx * 4] = make_float4(u0.y, u1.y, u2.y, u3.y);
    }
}

// =====================================================================
// Kernel B: persistent split-K recurrent scan with tf32 mma.sync.
// 128 CTAs: kc = bid>>4 (K-chunk of 128), ct = bid&15 (64-col tile).
// Sync: nanosleep-backoff relaxed polls + one acquire; tflag merged to one
// counter per k-chunk (16 arrivals); DRAM stores moved off the critical path.
// =====================================================================
#define ALD 132   // padded smem row stride (floats) -> conflict-free fragment loads

__global__ __launch_bounds__(256) void rnn_scan_kernel(
    const float* __restrict__ ip, const float* __restrict__ Wr,
    const float* __restrict__ bias, float* __restrict__ hid)
{
    extern __shared__ float smem[];
    float* As = smem;              // [64][132] tf32(th) slice for this step
    float* Bs = smem + 64 * ALD;   // [64][132] tf32(Wr^T) persistent slice
    unsigned* Asu = (unsigned*)As;
    unsigned* Bsu = (unsigned*)Bs;

    const int tid = threadIdx.x;
    const int bid = blockIdx.x;     // 0..127
    const int kc  = bid >> 4;       // 0..7
    const int ct  = bid & 15;       // 0..15

    // ---- persistent B operand: Bs[c][k] = tf32(Wr[(kc*128+k)*1024 + ct*64 + c]) ----
#pragma unroll
    for (int ii = 0; ii < 8; ii++) {
        const int idx = tid + 256 * ii;        // 0..2047
        const int k = idx >> 4, c4 = idx & 15;
        const float4 v = __ldg((const float4*)&Wr[(size_t)(kc * 128 + k) * HID + ct * 64 + c4 * 4]);
        Bsu[(c4 * 4 + 0) * ALD + k] = cvt_tf32(v.x);
        Bsu[(c4 * 4 + 1) * ALD + k] = cvt_tf32(v.y);
        Bsu[(c4 * 4 + 2) * ALD + k] = cvt_tf32(v.z);
        Bsu[(c4 * 4 + 3) * ALD + k] = cvt_tf32(v.w);
    }

    // ---- MMA thread coords: 8 warps tile 64x64 as (4 m-groups x 2 n-groups) ----
    const int w    = tid >> 5;
    const int lane = tid & 31;
    const int m0 = (w & 3) * 16;
    const int n0 = (w >> 2) * 32;
    const int lr = lane >> 2;
    const int lc = lane & 3;

    // ---- reducer coords: this thread owns (b, c, c+1) ----
    const int b  = kc * 8 + (tid >> 5);
    const int cl = (tid & 31) * 2;            // local col (even)
    const int c  = ct * 64 + cl;
    const float2 biav = *(const float2*)&bias[c];
    // fragment reverse-map index for (b, cl) within a producer's 4096-float block
    const int fw    = (b >> 4) + ((cl >> 5) << 2);
    const int fr    = b & 15;
    const int fcc   = cl & 31;
    const int fidx  = fw * 512 + (fcc >> 3) * 128 + ((fr & 7) * 4 + ((fcc & 7) >> 1)) * 4 + 2 * (fr >> 3);

    // tflag for the th slice this CTA CONTRIBUTES to: k-chunk = ct>>1 (16 arrivals each)
    unsigned* my_tpost_base = g_tflag;   // post target computed per t below

    float h0 = 0.f, h1 = 0.f;

    __syncthreads();

    for (int t = 0; t < TSQ; t++) {
        // prefetch ip for this step (independent of t-1 data)
        const size_t i0 = ((size_t)b * TSQ + t) * HID + c;
        const float2 ipv = *(const float2*)&ip[i0];

        float s0 = 0.f, s1 = 0.f;
        if (t > 0) {
            // ---- wait for th k-chunk kc of step t-1 (one counter, 16 arrivals) ----
            wait_flag(&g_tflag[(size_t)((t - 1) * 8 + kc) * FPAD], 16u);

            // ---- stage A = th[b][k], k in [128kc, +128), padded rows ----
#pragma unroll
            for (int ii = 0; ii < 8; ii++) {
                const int idx = tid + 256 * ii;    // 0..2047 float4s
                const int br = idx >> 5, k4 = idx & 31;
                const float4 v = __ldcg((const float4*)&g_thT[((size_t)(t - 1) * BATCH + br) * HID + kc * 128 + k4 * 4]);
                *(float4*)&As[br * ALD + k4 * 4] = v;
            }
            __syncthreads();

            // ---- tf32 MMA: D[64x64] partial over K=128 ----
            float d[4][4];
#pragma unroll
            for (int j = 0; j < 4; j++)
#pragma unroll
                for (int r = 0; r < 4; r++) d[j][r] = 0.f;

#pragma unroll
            for (int k8 = 0; k8 < 16; k8++) {
                const int kb = k8 * 8;
                const unsigned a0 = Asu[(m0 + lr) * ALD + kb + lc];
                const unsigned a1 = Asu[(m0 + lr + 8) * ALD + kb + lc];
                const unsigned a2 = Asu[(m0 + lr) * ALD + kb + lc + 4];
                const unsigned a3 = Asu[(m0 + lr + 8) * ALD + kb + lc + 4];
#pragma unroll
                for (int j = 0; j < 4; j++) {
                    const unsigned b0 = Bsu[(n0 + j * 8 + lr) * ALD + kb + lc];
                    const unsigned b1 = Bsu[(n0 + j * 8 + lr) * ALD + kb + lc + 4];
                    mma_tf32(d[j], a0, a1, a2, a3, b0, b1);
                }
            }

            // ---- store fragment partials (coalesced), double-buffered by parity ----
            float* gp = g_part + (size_t)(t & 1) * (128 * 4096) + (size_t)bid * 4096 + w * 512 + lane * 4;
#pragma unroll
            for (int j = 0; j < 4; j++)
                *(float4*)&gp[j * 128] = make_float4(d[j][0], d[j][1], d[j][2], d[j][3]);
            __threadfence();
            __syncthreads();   // single bar: covers MMA-done (As reuse) + fence-collective
            if (tid == 0) red_rel_add(&g_pflag[(size_t)(t * 16 + ct) * FPAD], 1u);

            // ---- wait all 8 K-chunk partials of this col-tile ----
            wait_flag(&g_pflag[(size_t)(t * 16 + ct) * FPAD], 8u);

            // ---- reduce: 8 fragment-mapped float2 reads ----
            const float* gpb = g_part + (size_t)(t & 1) * (128 * 4096);
#pragma unroll
            for (int q = 0; q < 8; q++) {
                const float2 p = __ldcg((const float2*)&gpb[(size_t)(q * 16 + ct) * 4096 + fidx]);
                s0 += p.x; s1 += p.y;
            }
        }

        // ---- state update for (b, c) and (b, c+1) ----
        h0 = (1.f - DT_A) * h0 + DT_A * (s0 + ipv.x + biav.x);
        h1 = (1.f - DT_A) * h1 + DT_A * (s1 + ipv.y + biav.y);
        const float th0 = tanhf(h0), th1 = tanhf(h1);
        // critical-path store: tf32 tanh for next-step MMA A operand, [t][b][k] layout
        *(float2*)&g_thT[((size_t)t * BATCH + b) * HID + c] =
            make_float2(__uint_as_float(cvt_tf32(th0)), __uint_as_float(cvt_tf32(th1)));

        __threadfence();
        __syncthreads();
        if (tid == 0) red_rel_add(&g_tflag[(size_t)(t * 8 + (ct >> 1)) * FPAD], 1u);

        // off-critical-path DRAM stores (consumed only by kernel C, kernel-boundary ordered)
        *(float2*)&hid[i0]    = make_float2(h0, h1);
        *(float2*)&g_thbt[i0] = make_float2(th0, th1);
    }
    (void)my_tpost_base;
}

// =====================================================================
// Kernel C: tot_output = tanh(hid) @ Wout  (fp32 tanh cached in g_thbt),
// plus transposed copy output_tensor[t][b][o].  FFMA2.
// =====================================================================
__global__ __launch_bounds__(256) void output_kernel(
    const float* __restrict__ Wout, float* __restrict__ tot_out, float* __restrict__ outT)
{
    __shared__ float As[BK * AS_LD];
    __shared__ float Bs[BK * BN];

    const int tid = threadIdx.x;
    const int r0  = blockIdx.y * BM;
    const int c0  = blockIdx.x * BN;

    const int arow = tid >> 2;
    const int ac4  = tid & 3;
    const int brow = tid >> 4;
    const int bc4  = tid & 15;
    const int tx = tid & 15;
    const int ty = tid >> 4;

    unsigned long long acc[4][4];
#pragma unroll
    for (int i = 0; i < 4; i++)
#pragma unroll
        for (int j = 0; j < 4; j++) acc[i][j] = 0ull;

    for (int k0 = 0; k0 < HID; k0 += BK) {
#pragma unroll
        for (int p = 0; p < 2; p++) {
            const int row = arow + p * 64;
            const float4 v = *(const float4*)&g_thbt[(size_t)(r0 + row) * HID + k0 + ac4 * 4];
            As[(ac4 * 4 + 0) * AS_LD + row] = v.x;
            As[(ac4 * 4 + 1) * AS_LD + row] = v.y;
            As[(ac4 * 4 + 2) * AS_LD + row] = v.z;
            As[(ac4 * 4 + 3) * AS_LD + row] = v.w;
        }
        *(float4*)&Bs[brow * BN + bc4 * 4] =
            *(const float4*)&Wout[(size_t)(k0 + brow) * OUTD + c0 + bc4 * 4];
        __syncthreads();

#pragma unroll
        for (int k = 0; k < BK; k++) {
            const ulonglong2 a01 = *(const ulonglong2*)&As[k * AS_LD + ty * 8];
            const ulonglong2 a23 = *(const ulonglong2*)&As[k * AS_LD + ty * 8 + 4];
            const float4 bf = *(const float4*)&Bs[k * BN + tx * 4];
            const unsigned long long b0 = pack2(bf.x), b1 = pack2(bf.y),
                                     b2 = pack2(bf.z), b3 = pack2(bf.w);
            fma2(acc[0][0], a01.x, b0); fma2(acc[0][1], a01.x, b1);
            fma2(acc[0][2], a01.x, b2); fma2(acc[0][3], a01.x, b3);
            fma2(acc[1][0], a01.y, b0); fma2(acc[1][1], a01.y, b1);
            fma2(acc[1][2], a01.y, b2); fma2(acc[1][3], a01.y, b3);
            fma2(acc[2][0], a23.x, b0); fma2(acc[2][1], a23.x, b1);
            fma2(acc[2][2], a23.x, b2); fma2(acc[2][3], a23.x, b3);
            fma2(acc[3][0], a23.y, b0); fma2(acc[3][1], a23.y, b1);
            fma2(acc[3][2], a23.y, b2); fma2(acc[3][3], a23.y, b3);
        }
        __syncthreads();
    }

#pragma unroll
    for (int rp = 0; rp < 4; rp++) {
        const int r  = r0 + ty * 8 + 2 * rp;
        const float2 u0 = unpack2(acc[rp][0]), u1 = unpack2(acc[rp][1]);
        const float2 u2 = unpack2(acc[rp][2]), u3 = unpack2(acc[rp][3]);
        const float4 v0 = make_float4(u0.x, u1.x, u2.x, u3.x);
        const float4 v1 = make_float4(u0.y, u1.y, u2.y, u3.y);
        const int b0i = r >> 9,        t0i = r & 511;
        const int b1i = (r + 1) >> 9,  t1i = (r + 1) & 511;
        *(float4*)&tot_out[(size_t)r * OUTD + c0 + tx * 4]       = v0;
        *(float4*)&tot_out[(size_t)(r + 1) * OUTD + c0 + tx * 4] = v1;
        *(float4*)&outT[((size_t)t0i * BATCH + b0i) * OUTD + c0 + tx * 4] = v0;
        *(float4*)&outT[((size_t)t1i * BATCH + b1i) * OUTD + c0 + tx * 4] = v1;
    }
}

// =====================================================================
// launch
// =====================================================================
extern "C" void kernel_launch(void* const* d_in, const int* in_sizes, int n_in,
                              void* d_out, int out_size)
{
    const float* x    = (const float*)d_in[0];
    const float* Win  = (const float*)d_in[1];
    const float* Wr   = (const float*)d_in[2];
    const float* bias = (const float*)d_in[3];
    const float* Wout = (const float*)d_in[4];

    float* out    = (float*)d_out;
    float* o_outT = out + O_OUTT;
    float* o_ip   = out + O_IP;
    float* o_hid  = out + O_HID;
    float* o_out  = out + O_OUT;

    // reset flag counters each launch (graph-capturable, deterministic replays)
    void* p0 = nullptr; void* p1 = nullptr;
    cudaGetSymbolAddress(&p0, g_pflag);
    cudaGetSymbolAddress(&p1, g_tflag);
    cudaMemsetAsync(p0, 0, (size_t)TSQ * 16 * FPAD * sizeof(unsigned));
    cudaMemsetAsync(p1, 0, (size_t)TSQ * 8 * FPAD * sizeof(unsigned));

    const int smemB = 2 * 64 * ALD * (int)sizeof(float);  // 67584
    cudaFuncSetAttribute(rnn_scan_kernel, cudaFuncAttributeMaxDynamicSharedMemorySize, smemB);

    // 1) input projection
    input_proj_kernel<<<dim3(HID / BN, (TSQ * BATCH) / BM), 256>>>(x, Win, o_ip);

    // 2) persistent split-K recurrent scan: 128 CTAs (all resident in wave 1)
    rnn_scan_kernel<<<128, 256, smemB>>>(o_ip, Wr, bias, o_hid);

    // 3) output projection + transpose
    output_kernel<<<dim3(OUTD / BN, (TSQ * BATCH) / BM), 256>>>(Wout, o_out, o_outT);
}

// round 11
// speedup vs baseline: 1.7385x; 1.2403x over previous
#include <cuda_runtime.h>
#include <math.h>

// ---------------- problem constants ----------------
#define TSQ   512
#define BATCH 64
#define INP   256
#define HID   1024
#define OUTD  256
#define DT_A  0.05f

// output buffer layout (floats): [output_tensor | input_proj | tot_rnnhid | tot_output]
static const size_t O_OUTT = 0;                                  // (512,64,256)
static const size_t O_IP   = (size_t)TSQ * BATCH * OUTD;         // (64,512,1024)
static const size_t O_HID  = O_IP  + (size_t)BATCH * TSQ * HID;  // (64,512,1024)
static const size_t O_OUT  = O_HID + (size_t)BATCH * TSQ * HID;  // (64,512,256)

// flag padding: one counter per 128-byte L2 line
#define FPAD 32

// ---------------- device scratch (static: no allocations allowed) ----------------
__device__ float    g_thT [(size_t)TSQ * BATCH * HID];   // tf32(tanh h): [t][b][k] (MMA A layout)
__device__ float    g_thbt[(size_t)BATCH * TSQ * HID];   // fp32 tanh(h): [b][t][k] (output-GEMM layout)
__device__ unsigned g_tflag[TSQ * 8 * FPAD];             // th-ready counters (per t, b-tile), 32 arrivals

// ---------------- f32x2 packed-FMA helpers (for kernels A/C) ----------------
__device__ __forceinline__ unsigned long long pack2(float v) {
    unsigned long long r;
    asm("mov.b64 %0, {%1, %1};" : "=l"(r) : "r"(__float_as_uint(v)));
    return r;
}
__device__ __forceinline__ void fma2(unsigned long long& d, unsigned long long a, unsigned long long b) {
    asm("fma.rn.f32x2 %0, %1, %2, %0;" : "+l"(d) : "l"(a), "l"(b));
}
__device__ __forceinline__ float2 unpack2(unsigned long long v) {
    unsigned lo, hi;
    asm("mov.b64 {%0, %1}, %2;" : "=r"(lo), "=r"(hi) : "l"(v));
    return make_float2(__uint_as_float(lo), __uint_as_float(hi));
}

// ---------------- sync helpers ----------------
__device__ __forceinline__ unsigned ld_relax(const unsigned* p) {
    unsigned v;
    asm volatile("ld.relaxed.gpu.global.u32 %0, [%1];" : "=r"(v) : "l"(p) : "memory");
    return v;
}
__device__ __forceinline__ unsigned ld_acq(const unsigned* p) {
    unsigned v;
    asm volatile("ld.acquire.gpu.global.u32 %0, [%1];" : "=r"(v) : "l"(p) : "memory");
    return v;
}
__device__ __forceinline__ void red_rel_add(unsigned* p, unsigned v) {
    asm volatile("red.release.gpu.global.add.u32 [%0], %1;" :: "l"(p), "r"(v) : "memory");
}
// relaxed poll with nanosleep backoff, then one acquire load to establish ordering
__device__ __forceinline__ void wait_flag(const unsigned* p, unsigned target) {
    if (ld_relax(p) < target) {
        do { __nanosleep(100); } while (ld_relax(p) < target);
    }
    (void)ld_acq(p);   // flag is monotonic: acquire-read synchronizes with the releases
}

// ---------------- tf32 helpers ----------------
__device__ __forceinline__ unsigned cvt_tf32(float f) {
    unsigned u;
    asm("cvt.rna.tf32.f32 %0, %1;" : "=r"(u) : "f"(f));
    return u;
}
__device__ __forceinline__ void mma_tf32(float d[4], unsigned a0, unsigned a1, unsigned a2, unsigned a3,
                                         unsigned b0, unsigned b1) {
    asm volatile(
        "mma.sync.aligned.m16n8k8.row.col.f32.tf32.tf32.f32 "
        "{%0,%1,%2,%3}, {%4,%5,%6,%7}, {%8,%9}, {%0,%1,%2,%3};"
        : "+f"(d[0]), "+f"(d[1]), "+f"(d[2]), "+f"(d[3])
        : "r"(a0), "r"(a1), "r"(a2), "r"(a3), "r"(b0), "r"(b1));
}

// =====================================================================
// Kernel A: input_proj[b][t][h] = sum_i x[t][b][i] * Win[i][h]
// =====================================================================
#define BM 128
#define BN 64
#define BK 16
#define AS_LD 136

__global__ __launch_bounds__(256) void input_proj_kernel(
    const float* __restrict__ x, const float* __restrict__ Win, float* __restrict__ ip)
{
    __shared__ float As[BK * AS_LD];
    __shared__ float Bs[BK * BN];

    const int tid = threadIdx.x;
    const int r0  = blockIdx.y * BM;
    const int c0  = blockIdx.x * BN;
    const int b   = r0 >> 9;
    const int t0  = r0 & 511;

    const int arow = tid >> 2;
    const int ac4  = tid & 3;
    const int brow = tid >> 4;
    const int bc4  = tid & 15;
    const int tx = tid & 15;
    const int ty = tid >> 4;

    unsigned long long acc[4][4];
#pragma unroll
    for (int i = 0; i < 4; i++)
#pragma unroll
        for (int j = 0; j < 4; j++) acc[i][j] = 0ull;

    for (int k0 = 0; k0 < INP; k0 += BK) {
#pragma unroll
        for (int p = 0; p < 2; p++) {
            const int row = arow + p * 64;
            const float4 v = *(const float4*)&x[((size_t)(t0 + row) * BATCH + b) * INP + k0 + ac4 * 4];
            As[(ac4 * 4 + 0) * AS_LD + row] = v.x;
            As[(ac4 * 4 + 1) * AS_LD + row] = v.y;
            As[(ac4 * 4 + 2) * AS_LD + row] = v.z;
            As[(ac4 * 4 + 3) * AS_LD + row] = v.w;
        }
        *(float4*)&Bs[brow * BN + bc4 * 4] =
            *(const float4*)&Win[(size_t)(k0 + brow) * HID + c0 + bc4 * 4];
        __syncthreads();

#pragma unroll
        for (int k = 0; k < BK; k++) {
            const ulonglong2 a01 = *(const ulonglong2*)&As[k * AS_LD + ty * 8];
            const ulonglong2 a23 = *(const ulonglong2*)&As[k * AS_LD + ty * 8 + 4];
            const float4 bf = *(const float4*)&Bs[k * BN + tx * 4];
            const unsigned long long b0 = pack2(bf.x), b1 = pack2(bf.y),
                                     b2 = pack2(bf.z), b3 = pack2(bf.w);
            fma2(acc[0][0], a01.x, b0); fma2(acc[0][1], a01.x, b1);
            fma2(acc[0][2], a01.x, b2); fma2(acc[0][3], a01.x, b3);
            fma2(acc[1][0], a01.y, b0); fma2(acc[1][1], a01.y, b1);
            fma2(acc[1][2], a01.y, b2); fma2(acc[1][3], a01.y, b3);
            fma2(acc[2][0], a23.x, b0); fma2(acc[2][1], a23.x, b1);
            fma2(acc[2][2], a23.x, b2); fma2(acc[2][3], a23.x, b3);
            fma2(acc[3][0], a23.y, b0); fma2(acc[3][1], a23.y, b1);
            fma2(acc[3][2], a23.y, b2); fma2(acc[3][3], a23.y, b3);
        }
        __syncthreads();
    }

#pragma unroll
    for (int rp = 0; rp < 4; rp++) {
        const int r = r0 + ty * 8 + 2 * rp;
        const float2 u0 = unpack2(acc[rp][0]), u1 = unpack2(acc[rp][1]);
        const float2 u2 = unpack2(acc[rp][2]), u3 = unpack2(acc[rp][3]);
        *(float4*)&ip[(size_t)r * HID + c0 + tx * 4]       = make_float4(u0.x, u1.x, u2.x, u3.x);
        *(float4*)&ip[(size_t)(r + 1) * HID + c0 + tx * 4] = make_float4(u0.y, u1.y, u2.y, u3.y);
    }
}

// =====================================================================
// Kernel B: persistent SINGLE-HOP recurrent scan with tf32 mma.sync.
// 128 CTAs: bt = bid>>5 (16-batch tile), ct = bid&31 (32-col tile).
// Each CTA owns FULL K=1024: Wr slice [1024][32] tf32 persists in smem
// (~132 KB). Per step: one global hop (th broadcast per b-tile group),
// K split 4-way across warps, reduced through 6 KB of smem.
// =====================================================================
#define ALD2 1028   // k stride (floats): 1024+4 -> conflict-free fragment loads

__global__ __launch_bounds__(256) void rnn_scan_kernel(
    const float* __restrict__ ip, const float* __restrict__ Wr,
    const float* __restrict__ bias, float* __restrict__ hid)
{
    extern __shared__ float smem[];
    float* As = smem;                    // [16][1028] tf32 th slice (this step's A)
    float* Bs = smem + 16 * ALD2;        // [32][1028] tf32 Wr^T persistent slice
    float* Rs = smem + 48 * ALD2;        // [1536] cross-warp K-reduce buffer
    unsigned* Asu = (unsigned*)As;
    unsigned* Bsu = (unsigned*)Bs;

    const int tid = threadIdx.x;
    const int bid = blockIdx.x;     // 0..127
    const int bt  = bid >> 5;       // 0..3   batch tile (16 rows)
    const int ct  = bid & 31;       // 0..31  col tile (32 cols)

    // ---- persistent B operand: Bs[c][k] = tf32(Wr[k][ct*32+c]) ----
#pragma unroll 4
    for (int ii = 0; ii < 32; ii++) {
        const int idx = tid + 256 * ii;        // 0..8191 float4s of Wr slice
        const int k = idx >> 3, c4 = idx & 7;
        const float4 v = __ldg((const float4*)&Wr[(size_t)k * HID + ct * 32 + c4 * 4]);
        Bsu[(c4 * 4 + 0) * ALD2 + k] = cvt_tf32(v.x);
        Bsu[(c4 * 4 + 1) * ALD2 + k] = cvt_tf32(v.y);
        Bsu[(c4 * 4 + 2) * ALD2 + k] = cvt_tf32(v.z);
        Bsu[(c4 * 4 + 3) * ALD2 + k] = cvt_tf32(v.w);
    }

    // ---- warp decomposition: w = kq*2 + jg; kq owns k range [kq*256,+256);
    //      jg owns n-tiles {jg*16 .. jg*16+15} (two m16n8 tiles) ----
    const int w    = tid >> 5;
    const int lane = tid & 31;
    const int kq   = w >> 1;        // 0..3
    const int jg   = w & 1;         // 0..1
    const int lr   = lane >> 2;     // 0..7
    const int lc   = lane & 3;      // 0..3

    // h-owner coords (warps 0-1 only): rows bt*16+lr, +8; cols ct*32+jg*16+j2*8+2lc,+1
    const int r0g = bt * 16 + lr;
    const int r1g = r0g + 8;

    float hreg[2][4];
#pragma unroll
    for (int j2 = 0; j2 < 2; j2++)
#pragma unroll
        for (int i = 0; i < 4; i++) hreg[j2][i] = 0.f;

    float2 bia2[2];
    if (w < 2) {
#pragma unroll
        for (int j2 = 0; j2 < 2; j2++)
            bia2[j2] = *(const float2*)&bias[ct * 32 + jg * 16 + j2 * 8 + 2 * lc];
    }

    __syncthreads();

    for (int t = 0; t < TSQ; t++) {
        // ---- ip prefetch (w<2 only; independent of t-1 data) ----
        float2 ipv[2][2];
        size_t ib[2][2];
        if (w < 2) {
#pragma unroll
            for (int j2 = 0; j2 < 2; j2++) {
                const int cj = ct * 32 + jg * 16 + j2 * 8 + 2 * lc;
                ib[j2][0] = ((size_t)r0g * TSQ + t) * HID + cj;
                ib[j2][1] = ((size_t)r1g * TSQ + t) * HID + cj;
                ipv[j2][0] = *(const float2*)&ip[ib[j2][0]];
                ipv[j2][1] = *(const float2*)&ip[ib[j2][1]];
            }
        }

        float d[2][4];
#pragma unroll
        for (int j2 = 0; j2 < 2; j2++)
#pragma unroll
            for (int i = 0; i < 4; i++) d[j2][i] = 0.f;

        if (t > 0) {
            // ---- single hop: wait for th b-tile bt of step t-1 (32 arrivals) ----
            wait_flag(&g_tflag[(size_t)((t - 1) * 4 + bt) * FPAD], 32u);

            // ---- stage A: th[t-1][bt*16..+16][0..1023] (64 KB, coalesced)
            //      4096 float4s: row = idx>>8 (256 float4s per 1024-float row) ----
#pragma unroll
            for (int i2 = 0; i2 < 16; i2++) {
                const int idx = tid + 256 * i2;    // 0..4095 float4s
                const int br = idx >> 8, k4 = idx & 255;
                const float4 v = __ldcg((const float4*)&g_thT[((size_t)(t - 1) * BATCH + bt * 16 + br) * HID + k4 * 4]);
                *(float4*)&As[br * ALD2 + k4 * 4] = v;
            }
            __syncthreads();

            // ---- tf32 MMA: this warp's K quarter, 2 n-tiles ----
            const int kbase = kq * 256;
#pragma unroll 4
            for (int k8 = 0; k8 < 32; k8++) {
                const int kb = kbase + k8 * 8;
                const unsigned a0 = Asu[lr * ALD2 + kb + lc];
                const unsigned a1 = Asu[(lr + 8) * ALD2 + kb + lc];
                const unsigned a2 = Asu[lr * ALD2 + kb + lc + 4];
                const unsigned a3 = Asu[(lr + 8) * ALD2 + kb + lc + 4];
                const unsigned b00 = Bsu[(jg * 16 + lr) * ALD2 + kb + lc];
                const unsigned b01 = Bsu[(jg * 16 + lr) * ALD2 + kb + lc + 4];
                mma_tf32(d[0], a0, a1, a2, a3, b00, b01);
                const unsigned b10 = Bsu[(jg * 16 + 8 + lr) * ALD2 + kb + lc];
                const unsigned b11 = Bsu[(jg * 16 + 8 + lr) * ALD2 + kb + lc + 4];
                mma_tf32(d[1], a0, a1, a2, a3, b10, b11);
            }

            // ---- cross-warp K reduce via smem: kq>0 store, kq==0 accumulate ----
            if (kq > 0) {
                float* rb = &Rs[(((kq - 1) * 2 + jg) * 32 + lane) * 8];
                *(float4*)&rb[0] = make_float4(d[0][0], d[0][1], d[0][2], d[0][3]);
                *(float4*)&rb[4] = make_float4(d[1][0], d[1][1], d[1][2], d[1][3]);
            }
            __syncthreads();
            if (w < 2) {
#pragma unroll
                for (int q = 0; q < 3; q++) {
                    const float* rb = &Rs[((q * 2 + jg) * 32 + lane) * 8];
                    const float4 p0 = *(const float4*)&rb[0];
                    const float4 p1 = *(const float4*)&rb[4];
                    d[0][0] += p0.x; d[0][1] += p0.y; d[0][2] += p0.z; d[0][3] += p0.w;
                    d[1][0] += p1.x; d[1][1] += p1.y; d[1][2] += p1.z; d[1][3] += p1.w;
                }
            }
        }

        // ---- state update + th store (warps 0-1 own the h state) ----
        float thv[2][4];
        if (w < 2) {
#pragma unroll
            for (int j2 = 0; j2 < 2; j2++) {
                hreg[j2][0] = (1.f - DT_A) * hreg[j2][0] + DT_A * (d[j2][0] + ipv[j2][0].x + bia2[j2].x);
                hreg[j2][1] = (1.f - DT_A) * hreg[j2][1] + DT_A * (d[j2][1] + ipv[j2][0].y + bia2[j2].y);
                hreg[j2][2] = (1.f - DT_A) * hreg[j2][2] + DT_A * (d[j2][2] + ipv[j2][1].x + bia2[j2].x);
                hreg[j2][3] = (1.f - DT_A) * hreg[j2][3] + DT_A * (d[j2][3] + ipv[j2][1].y + bia2[j2].y);
                thv[j2][0] = tanhf(hreg[j2][0]);
                thv[j2][1] = tanhf(hreg[j2][1]);
                thv[j2][2] = tanhf(hreg[j2][2]);
                thv[j2][3] = tanhf(hreg[j2][3]);
                // critical-path store: tf32 tanh, [t][b][k] layout
                const int cj = ct * 32 + jg * 16 + j2 * 8 + 2 * lc;
                *(float2*)&g_thT[((size_t)t * BATCH + r0g) * HID + cj] =
                    make_float2(__uint_as_float(cvt_tf32(thv[j2][0])), __uint_as_float(cvt_tf32(thv[j2][1])));
                *(float2*)&g_thT[((size_t)t * BATCH + r1g) * HID + cj] =
                    make_float2(__uint_as_float(cvt_tf32(thv[j2][2])), __uint_as_float(cvt_tf32(thv[j2][3])));
            }
            __threadfence();
        }
        __syncthreads();
        if (tid == 0) red_rel_add(&g_tflag[(size_t)(t * 4 + bt) * FPAD], 1u);

        // ---- off-critical-path DRAM stores (consumed only by kernel C) ----
        if (w < 2) {
#pragma unroll
            for (int j2 = 0; j2 < 2; j2++) {
                *(float2*)&hid[ib[j2][0]]    = make_float2(hreg[j2][0], hreg[j2][1]);
                *(float2*)&hid[ib[j2][1]]    = make_float2(hreg[j2][2], hreg[j2][3]);
                *(float2*)&g_thbt[ib[j2][0]] = make_float2(thv[j2][0], thv[j2][1]);
                *(float2*)&g_thbt[ib[j2][1]] = make_float2(thv[j2][2], thv[j2][3]);
            }
        }
    }
}

// =====================================================================
// Kernel C: tot_output = tanh(hid) @ Wout  (fp32 tanh cached in g_thbt),
// plus transposed copy output_tensor[t][b][o].  FFMA2.
// =====================================================================
__global__ __launch_bounds__(256) void output_kernel(
    const float* __restrict__ Wout, float* __restrict__ tot_out, float* __restrict__ outT)
{
    __shared__ float As[BK * AS_LD];
    __shared__ float Bs[BK * BN];

    const int tid = threadIdx.x;
    const int r0  = blockIdx.y * BM;
    const int c0  = blockIdx.x * BN;

    const int arow = tid >> 2;
    const int ac4  = tid & 3;
    const int brow = tid >> 4;
    const int bc4  = tid & 15;
    const int tx = tid & 15;
    const int ty = tid >> 4;

    unsigned long long acc[4][4];
#pragma unroll
    for (int i = 0; i < 4; i++)
#pragma unroll
        for (int j = 0; j < 4; j++) acc[i][j] = 0ull;

    for (int k0 = 0; k0 < HID; k0 += BK) {
#pragma unroll
        for (int p = 0; p < 2; p++) {
            const int row = arow + p * 64;
            const float4 v = *(const float4*)&g_thbt[(size_t)(r0 + row) * HID + k0 + ac4 * 4];
            As[(ac4 * 4 + 0) * AS_LD + row] = v.x;
            As[(ac4 * 4 + 1) * AS_LD + row] = v.y;
            As[(ac4 * 4 + 2) * AS_LD + row] = v.z;
            As[(ac4 * 4 + 3) * AS_LD + row] = v.w;
        }
        *(float4*)&Bs[brow * BN + bc4 * 4] =
            *(const float4*)&Wout[(size_t)(k0 + brow) * OUTD + c0 + bc4 * 4];
        __syncthreads();

#pragma unroll
        for (int k = 0; k < BK; k++) {
            const ulonglong2 a01 = *(const ulonglong2*)&As[k * AS_LD + ty * 8];
            const ulonglong2 a23 = *(const ulonglong2*)&As[k * AS_LD + ty * 8 + 4];
            const float4 bf = *(const float4*)&Bs[k * BN + tx * 4];
            const unsigned long long b0 = pack2(bf.x), b1 = pack2(bf.y),
                                     b2 = pack2(bf.z), b3 = pack2(bf.w);
            fma2(acc[0][0], a01.x, b0); fma2(acc[0][1], a01.x, b1);
            fma2(acc[0][2], a01.x, b2); fma2(acc[0][3], a01.x, b3);
            fma2(acc[1][0], a01.y, b0); fma2(acc[1][1], a01.y, b1);
            fma2(acc[1][2], a01.y, b2); fma2(acc[1][3], a01.y, b3);
            fma2(acc[2][0], a23.x, b0); fma2(acc[2][1], a23.x, b1);
            fma2(acc[2][2], a23.x, b2); fma2(acc[2][3], a23.x, b3);
            fma2(acc[3][0], a23.y, b0); fma2(acc[3][1], a23.y, b1);
            fma2(acc[3][2], a23.y, b2); fma2(acc[3][3], a23.y, b3);
        }
        __syncthreads();
    }

#pragma unroll
    for (int rp = 0; rp < 4; rp++) {
        const int r  = r0 + ty * 8 + 2 * rp;
        const float2 u0 = unpack2(acc[rp][0]), u1 = unpack2(acc[rp][1]);
        const float2 u2 = unpack2(acc[rp][2]), u3 = unpack2(acc[rp][3]);
        const float4 v0 = make_float4(u0.x, u1.x, u2.x, u3.x);
        const float4 v1 = make_float4(u0.y, u1.y, u2.y, u3.y);
        const int b0i = r >> 9,        t0i = r & 511;
        const int b1i = (r + 1) >> 9,  t1i = (r + 1) & 511;
        *(float4*)&tot_out[(size_t)r * OUTD + c0 + tx * 4]       = v0;
        *(float4*)&tot_out[(size_t)(r + 1) * OUTD + c0 + tx * 4] = v1;
        *(float4*)&outT[((size_t)t0i * BATCH + b0i) * OUTD + c0 + tx * 4] = v0;
        *(float4*)&outT[((size_t)t1i * BATCH + b1i) * OUTD + c0 + tx * 4] = v1;
    }
}

// =====================================================================
// launch
// =====================================================================
extern "C" void kernel_launch(void* const* d_in, const int* in_sizes, int n_in,
                              void* d_out, int out_size)
{
    const float* x    = (const float*)d_in[0];
    const float* Win  = (const float*)d_in[1];
    const float* Wr   = (const float*)d_in[2];
    const float* bias = (const float*)d_in[3];
    const float* Wout = (const float*)d_in[4];

    float* out    = (float*)d_out;
    float* o_outT = out + O_OUTT;
    float* o_ip   = out + O_IP;
    float* o_hid  = out + O_HID;
    float* o_out  = out + O_OUT;

    // reset flag counters each launch (graph-capturable, deterministic replays)
    void* p1 = nullptr;
    cudaGetSymbolAddress(&p1, g_tflag);
    cudaMemsetAsync(p1, 0, (size_t)TSQ * 8 * FPAD * sizeof(unsigned));

    // smem: As 16*1028 + Bs 32*1028 + Rs 1536 floats = 203520 bytes
    const int smemB = (48 * ALD2 + 1536) * (int)sizeof(float);
    cudaFuncSetAttribute(rnn_scan_kernel, cudaFuncAttributeMaxDynamicSharedMemorySize, smemB);

    // 1) input projection
    input_proj_kernel<<<dim3(HID / BN, (TSQ * BATCH) / BM), 256>>>(x, Win, o_ip);

    // 2) persistent single-hop recurrent scan: 128 CTAs (all resident in wave 1)
    rnn_scan_kernel<<<128, 256, smemB>>>(o_ip, Wr, bias, o_hid);

    // 3) output projection + transpose
    output_kernel<<<dim3(OUTD / BN, (TSQ * BATCH) / BM), 256>>>(Wout, o_out, o_outT);
}

// round 13
// speedup vs baseline: 2.3182x; 1.3335x over previous
#include <cuda_runtime.h>
#include <cuda_bf16.h>
#include <math.h>

// ---------------- problem constants ----------------
#define TSQ   512
#define BATCH 64
#define INP   256
#define HID   1024
#define OUTD  256
#define DT_A  0.05f

// output buffer layout (floats): [output_tensor | input_proj | tot_rnnhid | tot_output]
static const size_t O_OUTT = 0;                                  // (512,64,256)
static const size_t O_IP   = (size_t)TSQ * BATCH * OUTD;         // (64,512,1024)
static const size_t O_HID  = O_IP  + (size_t)BATCH * TSQ * HID;  // (64,512,1024)
static const size_t O_OUT  = O_HID + (size_t)BATCH * TSQ * HID;  // (64,512,256)

// flag padding: one counter per 128-byte L2 line
#define FPAD 32

// ---------------- device scratch (static: no allocations allowed) ----------------
__device__ __nv_bfloat16 g_thB[(size_t)TSQ * BATCH * HID];  // bf16 tanh(h): [t][b][k] (MMA A layout)
__device__ float         g_thbt[(size_t)BATCH * TSQ * HID]; // fp32 tanh(h): [b][t][k] (output-GEMM layout)
__device__ unsigned      g_tflag[TSQ * 8 * FPAD];           // th-ready counters (per t, b-tile), 32 arrivals

// ---------------- f32x2 packed-FMA helpers (for kernels A/C) ----------------
__device__ __forceinline__ unsigned long long pack2(float v) {
    unsigned long long r;
    asm("mov.b64 %0, {%1, %1};" : "=l"(r) : "r"(__float_as_uint(v)));
    return r;
}
__device__ __forceinline__ void fma2(unsigned long long& d, unsigned long long a, unsigned long long b) {
    asm("fma.rn.f32x2 %0, %1, %2, %0;" : "+l"(d) : "l"(a), "l"(b));
}
__device__ __forceinline__ float2 unpack2(unsigned long long v) {
    unsigned lo, hi;
    asm("mov.b64 {%0, %1}, %2;" : "=r"(lo), "=r"(hi) : "l"(v));
    return make_float2(__uint_as_float(lo), __uint_as_float(hi));
}

// ---------------- sync helpers ----------------
__device__ __forceinline__ unsigned ld_relax(const unsigned* p) {
    unsigned v;
    asm volatile("ld.relaxed.gpu.global.u32 %0, [%1];" : "=r"(v) : "l"(p) : "memory");
    return v;
}
__device__ __forceinline__ unsigned ld_acq(const unsigned* p) {
    unsigned v;
    asm volatile("ld.acquire.gpu.global.u32 %0, [%1];" : "=r"(v) : "l"(p) : "memory");
    return v;
}
__device__ __forceinline__ void red_rel_add(unsigned* p, unsigned v) {
    asm volatile("red.release.gpu.global.add.u32 [%0], %1;" :: "l"(p), "r"(v) : "memory");
}
// relaxed poll with nanosleep backoff, then one acquire load to establish ordering
__device__ __forceinline__ void wait_flag(const unsigned* p, unsigned target) {
    if (ld_relax(p) < target) {
        do { __nanosleep(100); } while (ld_relax(p) < target);
    }
    (void)ld_acq(p);   // flag is monotonic: acquire-read synchronizes with the releases
}

// ---------------- bf16 helpers ----------------
// pack two floats into bf16x2: lo -> bits[15:0], hi -> bits[31:16]
__device__ __forceinline__ unsigned pack_bf16x2(float lo, float hi) {
    unsigned r;
    asm("cvt.rn.bf16x2.f32 %0, %1, %2;" : "=r"(r) : "f"(hi), "f"(lo));
    return r;
}
__device__ __forceinline__ void mma_bf16(float d[4], unsigned a0, unsigned a1, unsigned a2, unsigned a3,
                                         unsigned b0, unsigned b1) {
    asm volatile(
        "mma.sync.aligned.m16n8k16.row.col.f32.bf16.bf16.f32 "
        "{%0,%1,%2,%3}, {%4,%5,%6,%7}, {%8,%9}, {%0,%1,%2,%3};"
        : "+f"(d[0]), "+f"(d[1]), "+f"(d[2]), "+f"(d[3])
        : "r"(a0), "r"(a1), "r"(a2), "r"(a3), "r"(b0), "r"(b1));
}

// =====================================================================
// Kernel A: input_proj[b][t][h] = sum_i x[t][b][i] * Win[i][h]
// =====================================================================
#define BM 128
#define BN 64
#define BK 16
#define AS_LD 136

__global__ __launch_bounds__(256) void input_proj_kernel(
    const float* __restrict__ x, const float* __restrict__ Win, float* __restrict__ ip)
{
    __shared__ float As[BK * AS_LD];
    __shared__ float Bs[BK * BN];

    const int tid = threadIdx.x;
    const int r0  = blockIdx.y * BM;
    const int c0  = blockIdx.x * BN;
    const int b   = r0 >> 9;
    const int t0  = r0 & 511;

    const int arow = tid >> 2;
    const int ac4  = tid & 3;
    const int brow = tid >> 4;
    const int bc4  = tid & 15;
    const int tx = tid & 15;
    const int ty = tid >> 4;

    unsigned long long acc[4][4];
#pragma unroll
    for (int i = 0; i < 4; i++)
#pragma unroll
        for (int j = 0; j < 4; j++) acc[i][j] = 0ull;

    for (int k0 = 0; k0 < INP; k0 += BK) {
#pragma unroll
        for (int p = 0; p < 2; p++) {
            const int row = arow + p * 64;
            const float4 v = *(const float4*)&x[((size_t)(t0 + row) * BATCH + b) * INP + k0 + ac4 * 4];
            As[(ac4 * 4 + 0) * AS_LD + row] = v.x;
            As[(ac4 * 4 + 1) * AS_LD + row] = v.y;
            As[(ac4 * 4 + 2) * AS_LD + row] = v.z;
            As[(ac4 * 4 + 3) * AS_LD + row] = v.w;
        }
        *(float4*)&Bs[brow * BN + bc4 * 4] =
            *(const float4*)&Win[(size_t)(k0 + brow) * HID + c0 + bc4 * 4];
        __syncthreads();

#pragma unroll
        for (int k = 0; k < BK; k++) {
            const ulonglong2 a01 = *(const ulonglong2*)&As[k * AS_LD + ty * 8];
            const ulonglong2 a23 = *(const ulonglong2*)&As[k * AS_LD + ty * 8 + 4];
            const float4 bf = *(const float4*)&Bs[k * BN + tx * 4];
            const unsigned long long b0 = pack2(bf.x), b1 = pack2(bf.y),
                                     b2 = pack2(bf.z), b3 = pack2(bf.w);
            fma2(acc[0][0], a01.x, b0); fma2(acc[0][1], a01.x, b1);
            fma2(acc[0][2], a01.x, b2); fma2(acc[0][3], a01.x, b3);
            fma2(acc[1][0], a01.y, b0); fma2(acc[1][1], a01.y, b1);
            fma2(acc[1][2], a01.y, b2); fma2(acc[1][3], a01.y, b3);
            fma2(acc[2][0], a23.x, b0); fma2(acc[2][1], a23.x, b1);
            fma2(acc[2][2], a23.x, b2); fma2(acc[2][3], a23.x, b3);
            fma2(acc[3][0], a23.y, b0); fma2(acc[3][1], a23.y, b1);
            fma2(acc[3][2], a23.y, b2); fma2(acc[3][3], a23.y, b3);
        }
        __syncthreads();
    }

#pragma unroll
    for (int rp = 0; rp < 4; rp++) {
        const int r = r0 + ty * 8 + 2 * rp;
        const float2 u0 = unpack2(acc[rp][0]), u1 = unpack2(acc[rp][1]);
        const float2 u2 = unpack2(acc[rp][2]), u3 = unpack2(acc[rp][3]);
        *(float4*)&ip[(size_t)r * HID + c0 + tx * 4]       = make_float4(u0.x, u1.x, u2.x, u3.x);
        *(float4*)&ip[(size_t)(r + 1) * HID + c0 + tx * 4] = make_float4(u0.y, u1.y, u2.y, u3.y);
    }
}

// =====================================================================
// Kernel B: persistent SINGLE-HOP recurrent scan with bf16 mma.sync (k16).
// 128 CTAs: bt = bid>>5 (16-batch tile), ct = bid&31 (32-col tile).
// Wr slice [32 cols][1024 k] bf16 persists in smem (~66 KB); per step:
// one global hop (bf16 th broadcast, 32 KB/CTA), K split 4-way across
// warps, reduced through 6 KB of smem.
// =====================================================================
#define AUW 516   // smem row stride in uints (= 1032 bf16); 516 mod 32 = 4 -> conflict-free

__global__ __launch_bounds__(256) void rnn_scan_kernel(
    const float* __restrict__ ip, const float* __restrict__ Wr,
    const float* __restrict__ bias, float* __restrict__ hid)
{
    extern __shared__ unsigned smemu[];
    unsigned* Asu = smemu;               // [16][516] uints: bf16 th slice (this step's A)
    unsigned* Bsu = smemu + 16 * AUW;    // [32][516] uints: bf16 Wr^T persistent slice
    float*    Rs  = (float*)(smemu + 48 * AUW);   // [1536] cross-warp K-reduce buffer

    const int tid = threadIdx.x;
    const int bid = blockIdx.x;     // 0..127
    const int bt  = bid >> 5;       // 0..3   batch tile (16 rows)
    const int ct  = bid & 31;       // 0..31  col tile (32 cols)

    // ---- persistent B operand: Bs[c][k] = bf16(Wr[k][ct*32+c]) ----
    {
        unsigned short* bsh = (unsigned short*)Bsu;
#pragma unroll 4
        for (int ii = 0; ii < 32; ii++) {
            const int idx = tid + 256 * ii;        // 0..8191 float4s of Wr slice
            const int k = idx >> 3, c4 = idx & 7;
            const float4 v = __ldg((const float4*)&Wr[(size_t)k * HID + ct * 32 + c4 * 4]);
            bsh[(c4 * 4 + 0) * (2 * AUW) + k] = __bfloat16_as_ushort(__float2bfloat16(v.x));
            bsh[(c4 * 4 + 1) * (2 * AUW) + k] = __bfloat16_as_ushort(__float2bfloat16(v.y));
            bsh[(c4 * 4 + 2) * (2 * AUW) + k] = __bfloat16_as_ushort(__float2bfloat16(v.z));
            bsh[(c4 * 4 + 3) * (2 * AUW) + k] = __bfloat16_as_ushort(__float2bfloat16(v.w));
        }
    }

    // ---- warp decomposition: w = kq*2 + jg; kq owns k range [kq*256,+256);
    //      jg owns n-tiles {jg*16 .. jg*16+15} (two m16n8 tiles) ----
    const int w    = tid >> 5;
    const int lane = tid & 31;
    const int kq   = w >> 1;        // 0..3
    const int jg   = w & 1;         // 0..1
    const int lr   = lane >> 2;     // 0..7
    const int lc   = lane & 3;      // 0..3

    // h-owner coords (warps 0-1 only): rows bt*16+lr, +8; cols ct*32+jg*16+j2*8+2lc,+1
    const int r0g = bt * 16 + lr;
    const int r1g = r0g + 8;

    float hreg[2][4];
#pragma unroll
    for (int j2 = 0; j2 < 2; j2++)
#pragma unroll
        for (int i = 0; i < 4; i++) hreg[j2][i] = 0.f;

    float2 bia2[2];
    if (w < 2) {
#pragma unroll
        for (int j2 = 0; j2 < 2; j2++)
            bia2[j2] = *(const float2*)&bias[ct * 32 + jg * 16 + j2 * 8 + 2 * lc];
    }

    __syncthreads();

    for (int t = 0; t < TSQ; t++) {
        // ---- ip prefetch (w<2 only; independent of t-1 data) ----
        float2 ipv[2][2];
        size_t ib[2][2];
        if (w < 2) {
#pragma unroll
            for (int j2 = 0; j2 < 2; j2++) {
                const int cj = ct * 32 + jg * 16 + j2 * 8 + 2 * lc;
                ib[j2][0] = ((size_t)r0g * TSQ + t) * HID + cj;
                ib[j2][1] = ((size_t)r1g * TSQ + t) * HID + cj;
                ipv[j2][0] = *(const float2*)&ip[ib[j2][0]];
                ipv[j2][1] = *(const float2*)&ip[ib[j2][1]];
            }
        }

        float d[2][4];
#pragma unroll
        for (int j2 = 0; j2 < 2; j2++)
#pragma unroll
            for (int i = 0; i < 4; i++) d[j2][i] = 0.f;

        if (t > 0) {
            // ---- single hop: wait for th b-tile bt of step t-1 (32 arrivals) ----
            wait_flag(&g_tflag[(size_t)((t - 1) * 4 + bt) * FPAD], 32u);

            // ---- stage A: bf16 th[t-1][bt*16..+16][0..1023] (32 KB)
            //      16 rows x 128 uint4 per row = 2048 uint4: row = idx>>7 ----
            const uint4* src = (const uint4*)&g_thB[((size_t)(t - 1) * BATCH + bt * 16) * HID];
#pragma unroll
            for (int i2 = 0; i2 < 8; i2++) {
                const int idx = tid + 256 * i2;    // 0..2047 uint4
                const int br = idx >> 7, k4 = idx & 127;  // 128 uint4 per 1024-bf16 row
                const uint4 v = __ldcg(&src[(size_t)br * 128 + k4]);
                *(uint4*)&Asu[br * AUW + k4 * 4] = v;
            }
            __syncthreads();

            // ---- bf16 MMA (k16): this warp's K quarter, 2 n-tiles ----
            const int kb0 = kq * 128;   // uint base of K quarter (256 bf16)
#pragma unroll 4
            for (int kk = 0; kk < 16; kk++) {
                const int kb = kb0 + kk * 8;   // uint index of k16 block
                const unsigned a0 = Asu[lr * AUW + kb + lc];
                const unsigned a1 = Asu[(lr + 8) * AUW + kb + lc];
                const unsigned a2 = Asu[lr * AUW + kb + lc + 4];
                const unsigned a3 = Asu[(lr + 8) * AUW + kb + lc + 4];
                const unsigned b00 = Bsu[(jg * 16 + lr) * AUW + kb + lc];
                const unsigned b01 = Bsu[(jg * 16 + lr) * AUW + kb + lc + 4];
                mma_bf16(d[0], a0, a1, a2, a3, b00, b01);
                const unsigned b10 = Bsu[(jg * 16 + 8 + lr) * AUW + kb + lc];
                const unsigned b11 = Bsu[(jg * 16 + 8 + lr) * AUW + kb + lc + 4];
                mma_bf16(d[1], a0, a1, a2, a3, b10, b11);
            }

            // ---- cross-warp K reduce via smem: kq>0 store, kq==0 accumulate ----
            if (kq > 0) {
                float* rb = &Rs[(((kq - 1) * 2 + jg) * 32 + lane) * 8];
                *(float4*)&rb[0] = make_float4(d[0][0], d[0][1], d[0][2], d[0][3]);
                *(float4*)&rb[4] = make_float4(d[1][0], d[1][1], d[1][2], d[1][3]);
            }
            __syncthreads();
            if (w < 2) {
#pragma unroll
                for (int q = 0; q < 3; q++) {
                    const float* rb = &Rs[((q * 2 + jg) * 32 + lane) * 8];
                    const float4 p0 = *(const float4*)&rb[0];
                    const float4 p1 = *(const float4*)&rb[4];
                    d[0][0] += p0.x; d[0][1] += p0.y; d[0][2] += p0.z; d[0][3] += p0.w;
                    d[1][0] += p1.x; d[1][1] += p1.y; d[1][2] += p1.z; d[1][3] += p1.w;
                }
            }
        }

        // ---- state update + th store (warps 0-1 own the h state) ----
        float thv[2][4];
        if (w < 2) {
#pragma unroll
            for (int j2 = 0; j2 < 2; j2++) {
                hreg[j2][0] = (1.f - DT_A) * hreg[j2][0] + DT_A * (d[j2][0] + ipv[j2][0].x + bia2[j2].x);
                hreg[j2][1] = (1.f - DT_A) * hreg[j2][1] + DT_A * (d[j2][1] + ipv[j2][0].y + bia2[j2].y);
                hreg[j2][2] = (1.f - DT_A) * hreg[j2][2] + DT_A * (d[j2][2] + ipv[j2][1].x + bia2[j2].x);
                hreg[j2][3] = (1.f - DT_A) * hreg[j2][3] + DT_A * (d[j2][3] + ipv[j2][1].y + bia2[j2].y);
                thv[j2][0] = tanhf(hreg[j2][0]);
                thv[j2][1] = tanhf(hreg[j2][1]);
                thv[j2][2] = tanhf(hreg[j2][2]);
                thv[j2][3] = tanhf(hreg[j2][3]);
                // critical-path store: bf16x2 tanh, [t][b][k] layout (cj even)
                const int cj = ct * 32 + jg * 16 + j2 * 8 + 2 * lc;
                *(unsigned*)&g_thB[((size_t)t * BATCH + r0g) * HID + cj] =
                    pack_bf16x2(thv[j2][0], thv[j2][1]);
                *(unsigned*)&g_thB[((size_t)t * BATCH + r1g) * HID + cj] =
                    pack_bf16x2(thv[j2][2], thv[j2][3]);
            }
            __threadfence();
        }
        __syncthreads();
        if (tid == 0) red_rel_add(&g_tflag[(size_t)(t * 4 + bt) * FPAD], 1u);

        // ---- off-critical-path DRAM stores (consumed only by kernel C) ----
        if (w < 2) {
#pragma unroll
            for (int j2 = 0; j2 < 2; j2++) {
                *(float2*)&hid[ib[j2][0]]    = make_float2(hreg[j2][0], hreg[j2][1]);
                *(float2*)&hid[ib[j2][1]]    = make_float2(hreg[j2][2], hreg[j2][3]);
                *(float2*)&g_thbt[ib[j2][0]] = make_float2(thv[j2][0], thv[j2][1]);
                *(float2*)&g_thbt[ib[j2][1]] = make_float2(thv[j2][2], thv[j2][3]);
            }
        }
    }
}

// =====================================================================
// Kernel C: tot_output = tanh(hid) @ Wout  (fp32 tanh cached in g_thbt),
// plus transposed copy output_tensor[t][b][o].  FFMA2.
// =====================================================================
__global__ __launch_bounds__(256) void output_kernel(
    const float* __restrict__ Wout, float* __restrict__ tot_out, float* __restrict__ outT)
{
    __shared__ float As[BK * AS_LD];
    __shared__ float Bs[BK * BN];

    const int tid = threadIdx.x;
    const int r0  = blockIdx.y * BM;
    const int c0  = blockIdx.x * BN;

    const int arow = tid >> 2;
    const int ac4  = tid & 3;
    const int brow = tid >> 4;
    const int bc4  = tid & 15;
    const int tx = tid & 15;
    const int ty = tid >> 4;

    unsigned long long acc[4][4];
#pragma unroll
    for (int i = 0; i < 4; i++)
#pragma unroll
        for (int j = 0; j < 4; j++) acc[i][j] = 0ull;

    for (int k0 = 0; k0 < HID; k0 += BK) {
#pragma unroll
        for (int p = 0; p < 2; p++) {
            const int row = arow + p * 64;
            const float4 v = *(const float4*)&g_thbt[(size_t)(r0 + row) * HID + k0 + ac4 * 4];
            As[(ac4 * 4 + 0) * AS_LD + row] = v.x;
            As[(ac4 * 4 + 1) * AS_LD + row] = v.y;
            As[(ac4 * 4 + 2) * AS_LD + row] = v.z;
            As[(ac4 * 4 + 3) * AS_LD + row] = v.w;
        }
        *(float4*)&Bs[brow * BN + bc4 * 4] =
            *(const float4*)&Wout[(size_t)(k0 + brow) * OUTD + c0 + bc4 * 4];
        __syncthreads();

#pragma unroll
        for (int k = 0; k < BK; k++) {
            const ulonglong2 a01 = *(const ulonglong2*)&As[k * AS_LD + ty * 8];
            const ulonglong2 a23 = *(const ulonglong2*)&As[k * AS_LD + ty * 8 + 4];
            const float4 bf = *(const float4*)&Bs[k * BN + tx * 4];
            const unsigned long long b0 = pack2(bf.x), b1 = pack2(bf.y),
                                     b2 = pack2(bf.z), b3 = pack2(bf.w);
            fma2(acc[0][0], a01.x, b0); fma2(acc[0][1], a01.x, b1);
            fma2(acc[0][2], a01.x, b2); fma2(acc[0][3], a01.x, b3);
            fma2(acc[1][0], a01.y, b0); fma2(acc[1][1], a01.y, b1);
            fma2(acc[1][2], a01.y, b2); fma2(acc[1][3], a01.y, b3);
            fma2(acc[2][0], a23.x, b0); fma2(acc[2][1], a23.x, b1);
            fma2(acc[2][2], a23.x, b2); fma2(acc[2][3], a23.x, b3);
            fma2(acc[3][0], a23.y, b0); fma2(acc[3][1], a23.y, b1);
            fma2(acc[3][2], a23.y, b2); fma2(acc[3][3], a23.y, b3);
        }
        __syncthreads();
    }

#pragma unroll
    for (int rp = 0; rp < 4; rp++) {
        const int r  = r0 + ty * 8 + 2 * rp;
        const float2 u0 = unpack2(acc[rp][0]), u1 = unpack2(acc[rp][1]);
        const float2 u2 = unpack2(acc[rp][2]), u3 = unpack2(acc[rp][3]);
        const float4 v0 = make_float4(u0.x, u1.x, u2.x, u3.x);
        const float4 v1 = make_float4(u0.y, u1.y, u2.y, u3.y);
        const int b0i = r >> 9,        t0i = r & 511;
        const int b1i = (r + 1) >> 9,  t1i = (r + 1) & 511;
        *(float4*)&tot_out[(size_t)r * OUTD + c0 + tx * 4]       = v0;
        *(float4*)&tot_out[(size_t)(r + 1) * OUTD + c0 + tx * 4] = v1;
        *(float4*)&outT[((size_t)t0i * BATCH + b0i) * OUTD + c0 + tx * 4] = v0;
        *(float4*)&outT[((size_t)t1i * BATCH + b1i) * OUTD + c0 + tx * 4] = v1;
    }
}

// =====================================================================
// launch
// =====================================================================
extern "C" void kernel_launch(void* const* d_in, const int* in_sizes, int n_in,
                              void* d_out, int out_size)
{
    const float* x    = (const float*)d_in[0];
    const float* Win  = (const float*)d_in[1];
    const float* Wr   = (const float*)d_in[2];
    const float* bias = (const float*)d_in[3];
    const float* Wout = (const float*)d_in[4];

    float* out    = (float*)d_out;
    float* o_outT = out + O_OUTT;
    float* o_ip   = out + O_IP;
    float* o_hid  = out + O_HID;
    float* o_out  = out + O_OUT;

    // reset flag counters each launch (graph-capturable, deterministic replays)
    void* p1 = nullptr;
    cudaGetSymbolAddress(&p1, g_tflag);
    cudaMemsetAsync(p1, 0, (size_t)TSQ * 8 * FPAD * sizeof(unsigned));

    // smem: As 16*516 + Bs 32*516 uints + Rs 1536 floats = 105216 bytes
    const int smemB = (48 * AUW) * 4 + 1536 * 4;
    cudaFuncSetAttribute(rnn_scan_kernel, cudaFuncAttributeMaxDynamicSharedMemorySize, smemB);

    // 1) input projection
    input_proj_kernel<<<dim3(HID / BN, (TSQ * BATCH) / BM), 256>>>(x, Win, o_ip);

    // 2) persistent single-hop recurrent scan: 128 CTAs (all resident in wave 1)
    rnn_scan_kernel<<<128, 256, smemB>>>(o_ip, Wr, bias, o_hid);

    // 3) output projection + transpose
    output_kernel<<<dim3(OUTD / BN, (TSQ * BATCH) / BM), 256>>>(Wout, o_out, o_outT);
}

// round 14
// speedup vs baseline: 2.9170x; 1.2583x over previous
#include <cuda_runtime.h>
#include <cuda_bf16.h>
#include <math.h>

// ---------------- problem constants ----------------
#define TSQ   512
#define BATCH 64
#define INP   256
#define HID   1024
#define OUTD  256
#define DT_A  0.05f

// output buffer layout (floats): [output_tensor | input_proj | tot_rnnhid | tot_output]
static const size_t O_OUTT = 0;                                  // (512,64,256)
static const size_t O_IP   = (size_t)TSQ * BATCH * OUTD;         // (64,512,1024)
static const size_t O_HID  = O_IP  + (size_t)BATCH * TSQ * HID;  // (64,512,1024)
static const size_t O_OUT  = O_HID + (size_t)BATCH * TSQ * HID;  // (64,512,256)

// flag padding: one counter per 128-byte L2 line
#define FPAD 32

// ---------------- device scratch (static: no allocations allowed) ----------------
__device__ __nv_bfloat16 g_thB[(size_t)TSQ * BATCH * HID];  // bf16 tanh(h): [t][b][k] (MMA A layout)
__device__ float         g_thbt[(size_t)BATCH * TSQ * HID]; // fp32 tanh(h): [b][t][k] (output-GEMM layout)
__device__ unsigned      g_tflag[TSQ * 8 * FPAD];           // th-ready counters (per t, b-tile), 32 arrivals
__device__ float         g_WinT [(size_t)HID * INP];        // tf32(Win^T):  [h][i]
__device__ float         g_WoutT[(size_t)OUTD * HID];       // tf32(Wout^T): [o][h]

// ---------------- sync helpers ----------------
__device__ __forceinline__ unsigned ld_relax(const unsigned* p) {
    unsigned v;
    asm volatile("ld.relaxed.gpu.global.u32 %0, [%1];" : "=r"(v) : "l"(p) : "memory");
    return v;
}
__device__ __forceinline__ unsigned ld_acq(const unsigned* p) {
    unsigned v;
    asm volatile("ld.acquire.gpu.global.u32 %0, [%1];" : "=r"(v) : "l"(p) : "memory");
    return v;
}
__device__ __forceinline__ void red_rel_add(unsigned* p, unsigned v) {
    asm volatile("red.release.gpu.global.add.u32 [%0], %1;" :: "l"(p), "r"(v) : "memory");
}
// relaxed poll with nanosleep backoff, then one acquire load to establish ordering
__device__ __forceinline__ void wait_flag(const unsigned* p, unsigned target) {
    if (ld_relax(p) < target) {
        do { __nanosleep(100); } while (ld_relax(p) < target);
    }
    (void)ld_acq(p);   // flag is monotonic: acquire-read synchronizes with the releases
}

// ---------------- bf16 / tf32 helpers ----------------
__device__ __forceinline__ unsigned pack_bf16x2(float lo, float hi) {
    unsigned r;
    asm("cvt.rn.bf16x2.f32 %0, %1, %2;" : "=r"(r) : "f"(hi), "f"(lo));
    return r;
}
__device__ __forceinline__ void mma_bf16(float d[4], unsigned a0, unsigned a1, unsigned a2, unsigned a3,
                                         unsigned b0, unsigned b1) {
    asm volatile(
        "mma.sync.aligned.m16n8k16.row.col.f32.bf16.bf16.f32 "
        "{%0,%1,%2,%3}, {%4,%5,%6,%7}, {%8,%9}, {%0,%1,%2,%3};"
        : "+f"(d[0]), "+f"(d[1]), "+f"(d[2]), "+f"(d[3])
        : "r"(a0), "r"(a1), "r"(a2), "r"(a3), "r"(b0), "r"(b1));
}
__device__ __forceinline__ unsigned cvt_tf32(float f) {
    unsigned u;
    asm("cvt.rna.tf32.f32 %0, %1;" : "=r"(u) : "f"(f));
    return u;
}
__device__ __forceinline__ void mma_tf32(float d[4], unsigned a0, unsigned a1, unsigned a2, unsigned a3,
                                         unsigned b0, unsigned b1) {
    asm volatile(
        "mma.sync.aligned.m16n8k8.row.col.f32.tf32.tf32.f32 "
        "{%0,%1,%2,%3}, {%4,%5,%6,%7}, {%8,%9}, {%0,%1,%2,%3};"
        : "+f"(d[0]), "+f"(d[1]), "+f"(d[2]), "+f"(d[3])
        : "r"(a0), "r"(a1), "r"(a2), "r"(a3), "r"(b0), "r"(b1));
}

// =====================================================================
// Kernel T: one-shot transpose + tf32 convert of Win and Wout.
// g_WinT[h][i] = tf32(Win[i][h]);  g_WoutT[o][h] = tf32(Wout[h][o]).
// Grid 512: blocks 0..255 -> Win (256x1024), 256..511 -> Wout (1024x256).
// =====================================================================
__global__ __launch_bounds__(256) void transpose_cvt_kernel(
    const float* __restrict__ Win, const float* __restrict__ Wout)
{
    __shared__ float tile[32][33];
    int bid = blockIdx.x;
    const float* src; float* dst; int R, C;
    if (bid < 256) { src = Win;  dst = g_WinT;  R = INP; C = HID; }
    else           { bid -= 256; src = Wout; dst = g_WoutT; R = HID; C = OUTD; }
    const int tilesC = C / 32;
    const int tr = bid / tilesC, tc = bid % tilesC;
    const int tx = threadIdx.x & 31, ty = threadIdx.x >> 5;   // 32 x 8

#pragma unroll
    for (int j = 0; j < 4; j++)
        tile[ty + 8 * j][tx] = src[(size_t)(tr * 32 + ty + 8 * j) * C + tc * 32 + tx];
    __syncthreads();
#pragma unroll
    for (int j = 0; j < 4; j++)
        dst[(size_t)(tc * 32 + ty + 8 * j) * R + tr * 32 + tx] =
            __uint_as_float(cvt_tf32(tile[tx][ty + 8 * j]));
}

// =====================================================================
// Kernel A: input_proj[b][t][h] = sum_i x[t][b][i] * Win[i][h]  (tf32 MMA)
// GEMM M=32768 (r=b*512+t), N=1024, K=256. CTA tile 128x64, BK=32.
// 8 warps = 4 m-groups x 2 n-groups; warp tile 32x32 (2 m16 x 4 n8).
// =====================================================================
#define TLD 36   // smem k-stride (floats); 36 mod 32 = 4 -> conflict-free frags

__global__ __launch_bounds__(256) void input_proj_kernel(
    const float* __restrict__ x, float* __restrict__ ip)
{
    __shared__ float As[128 * TLD];
    __shared__ float Bs[64 * TLD];
    unsigned* Asu = (unsigned*)As;
    unsigned* Bsu = (unsigned*)Bs;

    const int tid = threadIdx.x;
    const int r0  = blockIdx.y * 128;
    const int c0  = blockIdx.x * 64;
    const int b   = r0 >> 9;
    const int t0  = r0 & 511;

    const int w    = tid >> 5;
    const int lane = tid & 31;
    const int m0 = (w & 3) * 32;
    const int n0 = (w >> 2) * 32;
    const int lr = lane >> 2;
    const int lc = lane & 3;

    float d[2][4][4];
#pragma unroll
    for (int mt = 0; mt < 2; mt++)
#pragma unroll
        for (int nt = 0; nt < 4; nt++)
#pragma unroll
            for (int i = 0; i < 4; i++) d[mt][nt][i] = 0.f;

    for (int k0 = 0; k0 < INP; k0 += 32) {
        // stage A: 128 rows x 8 float4 (cvt to tf32)
#pragma unroll
        for (int it = 0; it < 4; it++) {
            const int idx = tid + 256 * it;
            const int row = idx >> 3, k4 = idx & 7;
            const float4 v = __ldg((const float4*)&x[((size_t)(t0 + row) * BATCH + b) * INP + k0 + k4 * 4]);
            uint4 u;
            u.x = cvt_tf32(v.x); u.y = cvt_tf32(v.y); u.z = cvt_tf32(v.z); u.w = cvt_tf32(v.w);
            *(uint4*)&Asu[row * TLD + k4 * 4] = u;
        }
        // stage B: 64 rows x 8 float4 (already tf32 in g_WinT)
#pragma unroll
        for (int it = 0; it < 2; it++) {
            const int idx = tid + 256 * it;
            const int row = idx >> 3, k4 = idx & 7;
            const float4 v = __ldg((const float4*)&g_WinT[(size_t)(c0 + row) * INP + k0 + k4 * 4]);
            *(float4*)&Bs[row * TLD + k4 * 4] = v;
        }
        __syncthreads();

#pragma unroll
        for (int kk = 0; kk < 4; kk++) {
            const int kb = kk * 8;
            unsigned a[2][4];
#pragma unroll
            for (int mt = 0; mt < 2; mt++) {
                const int mb = m0 + mt * 16;
                a[mt][0] = Asu[(mb + lr) * TLD + kb + lc];
                a[mt][1] = Asu[(mb + lr + 8) * TLD + kb + lc];
                a[mt][2] = Asu[(mb + lr) * TLD + kb + lc + 4];
                a[mt][3] = Asu[(mb + lr + 8) * TLD + kb + lc + 4];
            }
#pragma unroll
            for (int nt = 0; nt < 4; nt++) {
                const unsigned b0 = Bsu[(n0 + nt * 8 + lr) * TLD + kb + lc];
                const unsigned b1 = Bsu[(n0 + nt * 8 + lr) * TLD + kb + lc + 4];
                mma_tf32(d[0][nt], a[0][0], a[0][1], a[0][2], a[0][3], b0, b1);
                mma_tf32(d[1][nt], a[1][0], a[1][1], a[1][2], a[1][3], b0, b1);
            }
        }
        __syncthreads();
    }

    // epilogue: rows m0+mt*16+er(+8), cols n0+nt*8+ec(+1)
    const int er = lane >> 2, ec = 2 * (lane & 3);
#pragma unroll
    for (int mt = 0; mt < 2; mt++)
#pragma unroll
        for (int nt = 0; nt < 4; nt++) {
            const int r = r0 + m0 + mt * 16 + er;
            const int c = c0 + n0 + nt * 8 + ec;
            *(float2*)&ip[(size_t)r * HID + c]       = make_float2(d[mt][nt][0], d[mt][nt][1]);
            *(float2*)&ip[(size_t)(r + 8) * HID + c] = make_float2(d[mt][nt][2], d[mt][nt][3]);
        }
}

// =====================================================================
// Kernel B: persistent SINGLE-HOP recurrent scan with bf16 mma.sync (k16).
// (unchanged from round 13 — validated at 2402 us / 2.98e-5)
// =====================================================================
#define AUW 516   // smem row stride in uints (= 1032 bf16); 516 mod 32 = 4 -> conflict-free

__global__ __launch_bounds__(256) void rnn_scan_kernel(
    const float* __restrict__ ip, const float* __restrict__ Wr,
    const float* __restrict__ bias, float* __restrict__ hid)
{
    extern __shared__ unsigned smemu[];
    unsigned* Asu = smemu;               // [16][516] uints: bf16 th slice (this step's A)
    unsigned* Bsu = smemu + 16 * AUW;    // [32][516] uints: bf16 Wr^T persistent slice
    float*    Rs  = (float*)(smemu + 48 * AUW);   // [1536] cross-warp K-reduce buffer

    const int tid = threadIdx.x;
    const int bid = blockIdx.x;     // 0..127
    const int bt  = bid >> 5;       // 0..3   batch tile (16 rows)
    const int ct  = bid & 31;       // 0..31  col tile (32 cols)

    // ---- persistent B operand: Bs[c][k] = bf16(Wr[k][ct*32+c]) ----
    {
        unsigned short* bsh = (unsigned short*)Bsu;
#pragma unroll 4
        for (int ii = 0; ii < 32; ii++) {
            const int idx = tid + 256 * ii;        // 0..8191 float4s of Wr slice
            const int k = idx >> 3, c4 = idx & 7;
            const float4 v = __ldg((const float4*)&Wr[(size_t)k * HID + ct * 32 + c4 * 4]);
            bsh[(c4 * 4 + 0) * (2 * AUW) + k] = __bfloat16_as_ushort(__float2bfloat16(v.x));
            bsh[(c4 * 4 + 1) * (2 * AUW) + k] = __bfloat16_as_ushort(__float2bfloat16(v.y));
            bsh[(c4 * 4 + 2) * (2 * AUW) + k] = __bfloat16_as_ushort(__float2bfloat16(v.z));
            bsh[(c4 * 4 + 3) * (2 * AUW) + k] = __bfloat16_as_ushort(__float2bfloat16(v.w));
        }
    }

    const int w    = tid >> 5;
    const int lane = tid & 31;
    const int kq   = w >> 1;        // 0..3
    const int jg   = w & 1;         // 0..1
    const int lr   = lane >> 2;     // 0..7
    const int lc   = lane & 3;      // 0..3

    const int r0g = bt * 16 + lr;
    const int r1g = r0g + 8;

    float hreg[2][4];
#pragma unroll
    for (int j2 = 0; j2 < 2; j2++)
#pragma unroll
        for (int i = 0; i < 4; i++) hreg[j2][i] = 0.f;

    float2 bia2[2];
    if (w < 2) {
#pragma unroll
        for (int j2 = 0; j2 < 2; j2++)
            bia2[j2] = *(const float2*)&bias[ct * 32 + jg * 16 + j2 * 8 + 2 * lc];
    }

    __syncthreads();

    for (int t = 0; t < TSQ; t++) {
        float2 ipv[2][2];
        size_t ib[2][2];
        if (w < 2) {
#pragma unroll
            for (int j2 = 0; j2 < 2; j2++) {
                const int cj = ct * 32 + jg * 16 + j2 * 8 + 2 * lc;
                ib[j2][0] = ((size_t)r0g * TSQ + t) * HID + cj;
                ib[j2][1] = ((size_t)r1g * TSQ + t) * HID + cj;
                ipv[j2][0] = *(const float2*)&ip[ib[j2][0]];
                ipv[j2][1] = *(const float2*)&ip[ib[j2][1]];
            }
        }

        float d[2][4];
#pragma unroll
        for (int j2 = 0; j2 < 2; j2++)
#pragma unroll
            for (int i = 0; i < 4; i++) d[j2][i] = 0.f;

        if (t > 0) {
            wait_flag(&g_tflag[(size_t)((t - 1) * 4 + bt) * FPAD], 32u);

            const uint4* src = (const uint4*)&g_thB[((size_t)(t - 1) * BATCH + bt * 16) * HID];
#pragma unroll
            for (int i2 = 0; i2 < 8; i2++) {
                const int idx = tid + 256 * i2;
                const int br = idx >> 7, k4 = idx & 127;
                const uint4 v = __ldcg(&src[(size_t)br * 128 + k4]);
                *(uint4*)&Asu[br * AUW + k4 * 4] = v;
            }
            __syncthreads();

            const int kb0 = kq * 128;
#pragma unroll 4
            for (int kk = 0; kk < 16; kk++) {
                const int kb = kb0 + kk * 8;
                const unsigned a0 = Asu[lr * AUW + kb + lc];
                const unsigned a1 = Asu[(lr + 8) * AUW + kb + lc];
                const unsigned a2 = Asu[lr * AUW + kb + lc + 4];
                const unsigned a3 = Asu[(lr + 8) * AUW + kb + lc + 4];
                const unsigned b00 = Bsu[(jg * 16 + lr) * AUW + kb + lc];
                const unsigned b01 = Bsu[(jg * 16 + lr) * AUW + kb + lc + 4];
                mma_bf16(d[0], a0, a1, a2, a3, b00, b01);
                const unsigned b10 = Bsu[(jg * 16 + 8 + lr) * AUW + kb + lc];
                const unsigned b11 = Bsu[(jg * 16 + 8 + lr) * AUW + kb + lc + 4];
                mma_bf16(d[1], a0, a1, a2, a3, b10, b11);
            }

            if (kq > 0) {
                float* rb = &Rs[(((kq - 1) * 2 + jg) * 32 + lane) * 8];
                *(float4*)&rb[0] = make_float4(d[0][0], d[0][1], d[0][2], d[0][3]);
                *(float4*)&rb[4] = make_float4(d[1][0], d[1][1], d[1][2], d[1][3]);
            }
            __syncthreads();
            if (w < 2) {
#pragma unroll
                for (int q = 0; q < 3; q++) {
                    const float* rb = &Rs[((q * 2 + jg) * 32 + lane) * 8];
                    const float4 p0 = *(const float4*)&rb[0];
                    const float4 p1 = *(const float4*)&rb[4];
                    d[0][0] += p0.x; d[0][1] += p0.y; d[0][2] += p0.z; d[0][3] += p0.w;
                    d[1][0] += p1.x; d[1][1] += p1.y; d[1][2] += p1.z; d[1][3] += p1.w;
                }
            }
        }

        float thv[2][4];
        if (w < 2) {
#pragma unroll
            for (int j2 = 0; j2 < 2; j2++) {
                hreg[j2][0] = (1.f - DT_A) * hreg[j2][0] + DT_A * (d[j2][0] + ipv[j2][0].x + bia2[j2].x);
                hreg[j2][1] = (1.f - DT_A) * hreg[j2][1] + DT_A * (d[j2][1] + ipv[j2][0].y + bia2[j2].y);
                hreg[j2][2] = (1.f - DT_A) * hreg[j2][2] + DT_A * (d[j2][2] + ipv[j2][1].x + bia2[j2].x);
                hreg[j2][3] = (1.f - DT_A) * hreg[j2][3] + DT_A * (d[j2][3] + ipv[j2][1].y + bia2[j2].y);
                thv[j2][0] = tanhf(hreg[j2][0]);
                thv[j2][1] = tanhf(hreg[j2][1]);
                thv[j2][2] = tanhf(hreg[j2][2]);
                thv[j2][3] = tanhf(hreg[j2][3]);
                const int cj = ct * 32 + jg * 16 + j2 * 8 + 2 * lc;
                *(unsigned*)&g_thB[((size_t)t * BATCH + r0g) * HID + cj] =
                    pack_bf16x2(thv[j2][0], thv[j2][1]);
                *(unsigned*)&g_thB[((size_t)t * BATCH + r1g) * HID + cj] =
                    pack_bf16x2(thv[j2][2], thv[j2][3]);
            }
            __threadfence();
        }
        __syncthreads();
        if (tid == 0) red_rel_add(&g_tflag[(size_t)(t * 4 + bt) * FPAD], 1u);

        if (w < 2) {
#pragma unroll
            for (int j2 = 0; j2 < 2; j2++) {
                *(float2*)&hid[ib[j2][0]]    = make_float2(hreg[j2][0], hreg[j2][1]);
                *(float2*)&hid[ib[j2][1]]    = make_float2(hreg[j2][2], hreg[j2][3]);
                *(float2*)&g_thbt[ib[j2][0]] = make_float2(thv[j2][0], thv[j2][1]);
                *(float2*)&g_thbt[ib[j2][1]] = make_float2(thv[j2][2], thv[j2][3]);
            }
        }
    }
}

// =====================================================================
// Kernel C: tot_output = tanh(hid) @ Wout  (tf32 MMA, tanh in g_thbt),
// plus transposed copy output_tensor[t][b][o].
// GEMM M=32768 (r=b*512+t), N=256, K=1024. Same tiling as kernel A.
// =====================================================================
__global__ __launch_bounds__(256) void output_kernel(
    float* __restrict__ tot_out, float* __restrict__ outT)
{
    __shared__ float As[128 * TLD];
    __shared__ float Bs[64 * TLD];
    unsigned* Asu = (unsigned*)As;
    unsigned* Bsu = (unsigned*)Bs;

    const int tid = threadIdx.x;
    const int r0  = blockIdx.y * 128;
    const int c0  = blockIdx.x * 64;

    const int w    = tid >> 5;
    const int lane = tid & 31;
    const int m0 = (w & 3) * 32;
    const int n0 = (w >> 2) * 32;
    const int lr = lane >> 2;
    const int lc = lane & 3;

    float d[2][4][4];
#pragma unroll
    for (int mt = 0; mt < 2; mt++)
#pragma unroll
        for (int nt = 0; nt < 4; nt++)
#pragma unroll
            for (int i = 0; i < 4; i++) d[mt][nt][i] = 0.f;

    for (int k0 = 0; k0 < HID; k0 += 32) {
        // stage A from g_thbt (fp32 -> tf32)
#pragma unroll
        for (int it = 0; it < 4; it++) {
            const int idx = tid + 256 * it;
            const int row = idx >> 3, k4 = idx & 7;
            const float4 v = __ldcg((const float4*)&g_thbt[(size_t)(r0 + row) * HID + k0 + k4 * 4]);
            uint4 u;
            u.x = cvt_tf32(v.x); u.y = cvt_tf32(v.y); u.z = cvt_tf32(v.z); u.w = cvt_tf32(v.w);
            *(uint4*)&Asu[row * TLD + k4 * 4] = u;
        }
        // stage B from g_WoutT (already tf32)
#pragma unroll
        for (int it = 0; it < 2; it++) {
            const int idx = tid + 256 * it;
            const int row = idx >> 3, k4 = idx & 7;
            const float4 v = __ldg((const float4*)&g_WoutT[(size_t)(c0 + row) * HID + k0 + k4 * 4]);
            *(float4*)&Bs[row * TLD + k4 * 4] = v;
        }
        __syncthreads();

#pragma unroll
        for (int kk = 0; kk < 4; kk++) {
            const int kb = kk * 8;
            unsigned a[2][4];
#pragma unroll
            for (int mt = 0; mt < 2; mt++) {
                const int mb = m0 + mt * 16;
                a[mt][0] = Asu[(mb + lr) * TLD + kb + lc];
                a[mt][1] = Asu[(mb + lr + 8) * TLD + kb + lc];
                a[mt][2] = Asu[(mb + lr) * TLD + kb + lc + 4];
                a[mt][3] = Asu[(mb + lr + 8) * TLD + kb + lc + 4];
            }
#pragma unroll
            for (int nt = 0; nt < 4; nt++) {
                const unsigned b0 = Bsu[(n0 + nt * 8 + lr) * TLD + kb + lc];
                const unsigned b1 = Bsu[(n0 + nt * 8 + lr) * TLD + kb + lc + 4];
                mma_tf32(d[0][nt], a[0][0], a[0][1], a[0][2], a[0][3], b0, b1);
                mma_tf32(d[1][nt], a[1][0], a[1][1], a[1][2], a[1][3], b0, b1);
            }
        }
        __syncthreads();
    }

    // epilogue: tot_out[r][c] + transposed outT[t][b][c]
    const int er = lane >> 2, ec = 2 * (lane & 3);
#pragma unroll
    for (int mt = 0; mt < 2; mt++)
#pragma unroll
        for (int nt = 0; nt < 4; nt++) {
            const int r = r0 + m0 + mt * 16 + er;        // rows r, r+8 share b (tile within one b)
            const int c = c0 + n0 + nt * 8 + ec;
            const int bb = r >> 9, tt = r & 511;
            const float2 v0 = make_float2(d[mt][nt][0], d[mt][nt][1]);
            const float2 v1 = make_float2(d[mt][nt][2], d[mt][nt][3]);
            *(float2*)&tot_out[(size_t)r * OUTD + c]       = v0;
            *(float2*)&tot_out[(size_t)(r + 8) * OUTD + c] = v1;
            *(float2*)&outT[((size_t)tt * BATCH + bb) * OUTD + c]       = v0;
            *(float2*)&outT[((size_t)(tt + 8) * BATCH + bb) * OUTD + c] = v1;
        }
}

// =====================================================================
// launch
// =====================================================================
extern "C" void kernel_launch(void* const* d_in, const int* in_sizes, int n_in,
                              void* d_out, int out_size)
{
    const float* x    = (const float*)d_in[0];
    const float* Win  = (const float*)d_in[1];
    const float* Wr   = (const float*)d_in[2];
    const float* bias = (const float*)d_in[3];
    const float* Wout = (const float*)d_in[4];

    float* out    = (float*)d_out;
    float* o_outT = out + O_OUTT;
    float* o_ip   = out + O_IP;
    float* o_hid  = out + O_HID;
    float* o_out  = out + O_OUT;

    // reset flag counters each launch (graph-capturable, deterministic replays)
    void* p1 = nullptr;
    cudaGetSymbolAddress(&p1, g_tflag);
    cudaMemsetAsync(p1, 0, (size_t)TSQ * 8 * FPAD * sizeof(unsigned));

    const int smemB = (48 * AUW) * 4 + 1536 * 4;   // 105216 bytes
    cudaFuncSetAttribute(rnn_scan_kernel, cudaFuncAttributeMaxDynamicSharedMemorySize, smemB);

    // 0) one-shot transpose + tf32 convert of Win / Wout
    transpose_cvt_kernel<<<512, 256>>>(Win, Wout);

    // 1) input projection (tf32 tensor cores)
    input_proj_kernel<<<dim3(HID / 64, (TSQ * BATCH) / 128), 256>>>(x, o_ip);

    // 2) persistent single-hop recurrent scan: 128 CTAs (all resident in wave 1)
    rnn_scan_kernel<<<128, 256, smemB>>>(o_ip, Wr, bias, o_hid);

    // 3) output projection + transpose (tf32 tensor cores)
    output_kernel<<<dim3(OUTD / 64, (TSQ * BATCH) / 128), 256>>>(o_out, o_outT);
}